// round 1
// baseline (speedup 1.0000x reference)
#include <cuda_runtime.h>
#include <cuda_bf16.h>

// Problem constants
#define BB 8
#define QQ 64
#define CC 512
#define DD 512    // context size (= query size)
#define HH 256
#define EPSF 1e-5f

// Scratch (device globals — no allocation allowed)
__device__ float g_resq[BB * QQ * HH];        // [b][q][h]
__device__ float g_rescT[BB * HH * CC];       // [b][h][c]  (transposed for coalesced K3 reads)

__device__ __forceinline__ float tanh_approx(float x) {
    float y;
    asm("tanh.approx.f32 %0, %1;" : "=f"(y) : "f"(x));
    return y;
}

// ---------------------------------------------------------------------------
// K1: res_cT[b][h][c] = b_c[h] + sum_d W_c[h][d] * context[b][c][d]
// Tiled TN GEMM: 64x64 tile, K-tile 16, 256 threads, 4x4 per thread.
// grid = (C/64=8, H/64=4, B=8) = 256 blocks
// ---------------------------------------------------------------------------
__global__ void gemm_resc(const float* __restrict__ Wc,
                          const float* __restrict__ Ctx,
                          const float* __restrict__ bc)
{
    const int b  = blockIdx.z;
    const int h0 = blockIdx.y * 64;
    const int c0 = blockIdx.x * 64;
    __shared__ float As[16][68];  // [d][h]
    __shared__ float Bs[16][68];  // [d][c]

    const int tid = threadIdx.x;       // 0..255
    const int tx  = tid & 15;          // c group
    const int ty  = tid >> 4;          // h group
    const float* ctxb = Ctx + (size_t)b * CC * DD;

    float acc[4][4] = {};

    for (int k0 = 0; k0 < DD; k0 += 16) {
        #pragma unroll
        for (int i = 0; i < 4; i++) {
            int e  = tid + i * 256;        // 0..1023
            int rl = e >> 4;               // row within tile (0..63)
            int dl = e & 15;               // d within k-tile
            As[dl][rl] = Wc[(h0 + rl) * DD + k0 + dl];
            Bs[dl][rl] = ctxb[(c0 + rl) * DD + k0 + dl];
        }
        __syncthreads();
        #pragma unroll
        for (int d = 0; d < 16; d++) {
            float a[4], bv[4];
            #pragma unroll
            for (int i = 0; i < 4; i++) a[i]  = As[d][ty * 4 + i];
            #pragma unroll
            for (int j = 0; j < 4; j++) bv[j] = Bs[d][tx * 4 + j];
            #pragma unroll
            for (int i = 0; i < 4; i++)
                #pragma unroll
                for (int j = 0; j < 4; j++)
                    acc[i][j] += a[i] * bv[j];
        }
        __syncthreads();
    }

    float* outb = g_rescT + (size_t)b * HH * CC;
    #pragma unroll
    for (int i = 0; i < 4; i++) {
        int h = h0 + ty * 4 + i;
        float bias = bc[h];
        #pragma unroll
        for (int j = 0; j < 4; j++) {
            outb[h * CC + c0 + tx * 4 + j] = acc[i][j] + bias;
        }
    }
}

// ---------------------------------------------------------------------------
// K2: res_q[bq][h] = sum_d query[bq][d] * W_q[h][d]
// Same tile shape. grid = (H/64=4, BQ/64=8) = 32 blocks
// ---------------------------------------------------------------------------
__global__ void gemm_resq(const float* __restrict__ Qm,
                          const float* __restrict__ Wq)
{
    const int m0 = blockIdx.y * 64;   // bq
    const int n0 = blockIdx.x * 64;   // h
    __shared__ float As[16][68];      // [d][m]
    __shared__ float Bs[16][68];      // [d][n]

    const int tid = threadIdx.x;
    const int tx  = tid & 15;         // n group
    const int ty  = tid >> 4;         // m group

    float acc[4][4] = {};

    for (int k0 = 0; k0 < DD; k0 += 16) {
        #pragma unroll
        for (int i = 0; i < 4; i++) {
            int e  = tid + i * 256;
            int rl = e >> 4;
            int dl = e & 15;
            As[dl][rl] = Qm[(m0 + rl) * DD + k0 + dl];
            Bs[dl][rl] = Wq[(n0 + rl) * DD + k0 + dl];
        }
        __syncthreads();
        #pragma unroll
        for (int d = 0; d < 16; d++) {
            float a[4], bv[4];
            #pragma unroll
            for (int i = 0; i < 4; i++) a[i]  = As[d][ty * 4 + i];
            #pragma unroll
            for (int j = 0; j < 4; j++) bv[j] = Bs[d][tx * 4 + j];
            #pragma unroll
            for (int i = 0; i < 4; i++)
                #pragma unroll
                for (int j = 0; j < 4; j++)
                    acc[i][j] += a[i] * bv[j];
        }
        __syncthreads();
    }

    #pragma unroll
    for (int i = 0; i < 4; i++)
        #pragma unroll
        for (int j = 0; j < 4; j++)
            g_resq[(m0 + ty * 4 + i) * HH + n0 + tx * 4 + j] = acc[i][j];
}

// ---------------------------------------------------------------------------
// K3: fused logits (tanh over H) + softmax over C + output = weights @ context
// One block handles (b, q0, q0+1) for all 512 c. 512 threads, thread = c.
// grid = B * Q/2 = 256 blocks.
// ---------------------------------------------------------------------------
__global__ __launch_bounds__(512)
void attn_main(const float* __restrict__ Ctx,
               const float* __restrict__ Maskp,
               const float* __restrict__ Wo,
               const float* __restrict__ bo_p,
               float* __restrict__ out)
{
    const int blk = blockIdx.x;
    const int b   = blk >> 5;          // / 32
    const int q0  = (blk & 31) * 2;
    const int tid = threadIdx.x;       // = c

    __shared__ float sh_rq0[HH];
    __shared__ float sh_rq1[HH];
    __shared__ float sh_wo[HH];
    __shared__ float sh_w0[CC];
    __shared__ float sh_w1[CC];
    __shared__ float sh_part[2][16];
    __shared__ float sh_tot[2];

    if (tid < HH) {
        sh_rq0[tid] = g_resq[((b * QQ + q0)     ) * HH + tid];
        sh_rq1[tid] = g_resq[((b * QQ + q0 + 1) ) * HH + tid];
        sh_wo[tid]  = Wo[tid];
    }
    __syncthreads();

    // ---- phase 1: logits over H ----
    float acc0 = 0.f, acc1 = 0.f;
    const float* rc = g_rescT + (size_t)b * HH * CC + tid;
    #pragma unroll 4
    for (int h = 0; h < HH; h++) {
        float a = rc[h * CC];
        float w = sh_wo[h];
        acc0 += w * tanh_approx(a + sh_rq0[h]);
        acc1 += w * tanh_approx(a + sh_rq1[h]);
    }

    const float bo = __ldg(bo_p);
    const float m  = Maskp[b * CC + tid];
    float e0 = m * __expf(acc0 + bo);
    float e1 = m * __expf(acc1 + bo);

    // ---- softmax denominator (block reduce over 512) ----
    float s0 = e0, s1 = e1;
    #pragma unroll
    for (int off = 16; off > 0; off >>= 1) {
        s0 += __shfl_xor_sync(0xffffffffu, s0, off);
        s1 += __shfl_xor_sync(0xffffffffu, s1, off);
    }
    const int lane = tid & 31, wid = tid >> 5;
    if (lane == 0) { sh_part[0][wid] = s0; sh_part[1][wid] = s1; }
    __syncthreads();
    if (tid == 0) {
        float t0 = 0.f, t1 = 0.f;
        #pragma unroll
        for (int i = 0; i < 16; i++) { t0 += sh_part[0][i]; t1 += sh_part[1][i]; }
        sh_tot[0] = 1.f / (t0 + EPSF);
        sh_tot[1] = 1.f / (t1 + EPSF);
    }
    __syncthreads();

    float w0 = e0 * sh_tot[0];
    float w1 = e1 * sh_tot[1];

    // weights section of d_out (after output section)
    const int WOFF = BB * QQ * DD;
    out[WOFF + (b * QQ + q0    ) * CC + tid] = w0;
    out[WOFF + (b * QQ + q0 + 1) * CC + tid] = w1;

    sh_w0[tid] = w0;
    sh_w1[tid] = w1;
    __syncthreads();

    // ---- phase 2: output[q][d] = sum_c w[c] * ctx[b][c][d], d = tid ----
    float o0 = 0.f, o1 = 0.f;
    const float* cb = Ctx + (size_t)b * CC * DD + tid;
    #pragma unroll 4
    for (int c = 0; c < CC; c++) {
        float v = cb[c * DD];
        o0 += sh_w0[c] * v;
        o1 += sh_w1[c] * v;
    }
    out[(b * QQ + q0    ) * DD + tid] = o0;
    out[(b * QQ + q0 + 1) * DD + tid] = o1;
}

// ---------------------------------------------------------------------------
extern "C" void kernel_launch(void* const* d_in, const int* in_sizes, int n_in,
                              void* d_out, int out_size)
{
    const float* query   = (const float*)d_in[0];
    const float* context = (const float*)d_in[1];
    const float* mask    = (const float*)d_in[2];
    const float* W_c     = (const float*)d_in[3];
    const float* b_c     = (const float*)d_in[4];
    const float* W_q     = (const float*)d_in[5];
    const float* W_o     = (const float*)d_in[6];
    const float* b_o     = (const float*)d_in[7];
    float* out = (float*)d_out;

    dim3 g1(CC / 64, HH / 64, BB);     // 8 x 4 x 8 = 256 blocks
    gemm_resc<<<g1, 256>>>(W_c, context, b_c);

    dim3 g2(HH / 64, (BB * QQ) / 64);  // 4 x 8 = 32 blocks
    gemm_resq<<<g2, 256>>>(query, W_q);

    attn_main<<<BB * QQ / 2, 512>>>(context, mask, W_o, b_o, out);
}

// round 2
// speedup vs baseline: 1.2923x; 1.2923x over previous
#include <cuda_runtime.h>
#include <cuda_bf16.h>

// Problem constants
#define BB 8
#define QQ 64
#define CC 512
#define DD 512    // context size (= query size)
#define HH 256
#define EPSF 1e-5f

// Scratch (device globals — no allocation allowed)
__device__ float g_resq[BB * QQ * HH];        // [bq][h]
__device__ float g_rescT[BB * HH * CC];       // [b][h][c]

__device__ __forceinline__ float tanh_approx(float x) {
    float y;
    asm("tanh.approx.f32 %0, %1;" : "=f"(y) : "f"(x));
    return y;
}

// ---------------------------------------------------------------------------
// Fused GEMMs: one launch, 288 blocks.
//   blocks [0,256):  res_cT[b][h][c] = b_c[h] + Wc[h,:]·ctx[b][c,:]
//   blocks [256,288): res_q[bq][h]   = query[bq,:]·Wq[h,:]
// Both are 64x64 TN tiles over K=512, 256 threads, 4x4/thread,
// double-buffered smem, float4 global loads.
// ---------------------------------------------------------------------------
__global__ __launch_bounds__(256, 2)
void fused_gemms(const float* __restrict__ Wc,
                 const float* __restrict__ Ctx,
                 const float* __restrict__ bc,
                 const float* __restrict__ Qm,
                 const float* __restrict__ Wq)
{
    __shared__ float As[2][16][68];
    __shared__ float Bs[2][16][68];

    const int tid = threadIdx.x;       // 0..255
    const int tx  = tid & 15;          // col group (4 cols)
    const int ty  = tid >> 4;          // row group (4 rows)
    const int lr  = tid >> 2;          // load row 0..63
    const int ldg = tid & 3;           // load d-group (4 floats)

    const float *Ap, *Bp;
    const float* biasp = nullptr;
    float* outp;
    int ldo;

    const int blk = blockIdx.x;
    if (blk < 256) {
        const int b   = blk >> 5;
        const int rem = blk & 31;
        const int h0  = (rem >> 3) << 6;
        const int c0  = (rem & 7) << 6;
        Ap    = Wc + h0 * DD;
        Bp    = Ctx + ((size_t)b * CC + c0) * DD;
        outp  = g_rescT + (size_t)b * HH * CC + (size_t)h0 * CC + c0;
        ldo   = CC;
        biasp = bc + h0;
    } else {
        const int blk2 = blk - 256;
        const int m0   = (blk2 >> 2) << 6;   // bq
        const int n0   = (blk2 & 3) << 6;    // h
        Ap   = Qm + m0 * DD;
        Bp   = Wq + n0 * DD;
        outp = g_resq + m0 * HH + n0;
        ldo  = HH;
    }

    const float* arow = Ap + lr * DD + ldg * 4;
    const float* brow = Bp + lr * DD + ldg * 4;

    float acc[4][4] = {};

    // Prologue: stage 0
    {
        float4 a4 = *(const float4*)arow;
        float4 b4 = *(const float4*)brow;
        const int d0 = ldg * 4;
        As[0][d0+0][lr] = a4.x; As[0][d0+1][lr] = a4.y;
        As[0][d0+2][lr] = a4.z; As[0][d0+3][lr] = a4.w;
        Bs[0][d0+0][lr] = b4.x; Bs[0][d0+1][lr] = b4.y;
        Bs[0][d0+2][lr] = b4.z; Bs[0][d0+3][lr] = b4.w;
    }
    __syncthreads();

    int buf = 0;
    for (int k0 = 16; k0 <= DD; k0 += 16) {
        float4 na, nb;
        const bool more = (k0 < DD);
        if (more) {
            na = *(const float4*)(arow + k0);
            nb = *(const float4*)(brow + k0);
        }

        #pragma unroll
        for (int d = 0; d < 16; d++) {
            float4 av = *(const float4*)&As[buf][d][ty * 4];
            float4 bv = *(const float4*)&Bs[buf][d][tx * 4];
            acc[0][0] += av.x * bv.x; acc[0][1] += av.x * bv.y;
            acc[0][2] += av.x * bv.z; acc[0][3] += av.x * bv.w;
            acc[1][0] += av.y * bv.x; acc[1][1] += av.y * bv.y;
            acc[1][2] += av.y * bv.z; acc[1][3] += av.y * bv.w;
            acc[2][0] += av.z * bv.x; acc[2][1] += av.z * bv.y;
            acc[2][2] += av.z * bv.z; acc[2][3] += av.z * bv.w;
            acc[3][0] += av.w * bv.x; acc[3][1] += av.w * bv.y;
            acc[3][2] += av.w * bv.z; acc[3][3] += av.w * bv.w;
        }

        if (more) {
            const int nbuf = buf ^ 1;
            const int d0 = ldg * 4;
            As[nbuf][d0+0][lr] = na.x; As[nbuf][d0+1][lr] = na.y;
            As[nbuf][d0+2][lr] = na.z; As[nbuf][d0+3][lr] = na.w;
            Bs[nbuf][d0+0][lr] = nb.x; Bs[nbuf][d0+1][lr] = nb.y;
            Bs[nbuf][d0+2][lr] = nb.z; Bs[nbuf][d0+3][lr] = nb.w;
        }
        __syncthreads();
        buf ^= 1;
    }

    #pragma unroll
    for (int i = 0; i < 4; i++) {
        const float bi = biasp ? biasp[ty * 4 + i] : 0.f;
        float4 o;
        o.x = acc[i][0] + bi; o.y = acc[i][1] + bi;
        o.z = acc[i][2] + bi; o.w = acc[i][3] + bi;
        *(float4*)(outp + (ty * 4 + i) * ldo + tx * 4) = o;
    }
}

// ---------------------------------------------------------------------------
// K3: fused logits (tanh over H) + softmax over C + output = weights @ context
// One block per (b, q-group of 4). 512 threads, thread = c (phase 1/softmax)
// and thread = d (phase 2). grid = B*Q/4 = 128 blocks.
// ---------------------------------------------------------------------------
__global__ __launch_bounds__(512)
void attn_main(const float* __restrict__ Ctx,
               const float* __restrict__ Maskp,
               const float* __restrict__ Wo,
               const float* __restrict__ bo_p,
               float* __restrict__ out)
{
    const int blk = blockIdx.x;        // 0..127
    const int b   = blk >> 4;
    const int q0  = (blk & 15) * 4;
    const int tid = threadIdx.x;       // = c in phase 1, = d in phase 2

    __shared__ float4 sh_rq[HH];       // [h] -> res_q for 4 q's
    __shared__ float  sh_wo[HH];
    __shared__ float4 sh_w[CC];        // [c] -> weights for 4 q's
    __shared__ float  sh_part[4][16];
    __shared__ float  sh_tot[4];

    if (tid < HH) {
        float4 r;
        r.x = g_resq[(b * QQ + q0 + 0) * HH + tid];
        r.y = g_resq[(b * QQ + q0 + 1) * HH + tid];
        r.z = g_resq[(b * QQ + q0 + 2) * HH + tid];
        r.w = g_resq[(b * QQ + q0 + 3) * HH + tid];
        sh_rq[tid] = r;
        sh_wo[tid] = Wo[tid];
    }
    __syncthreads();

    // ---- phase 1: logits over H ----
    float a0 = 0.f, a1 = 0.f, a2 = 0.f, a3 = 0.f;
    const float* rc = g_rescT + (size_t)b * HH * CC + tid;
    #pragma unroll 4
    for (int h = 0; h < HH; h++) {
        const float a  = rc[(size_t)h * CC];
        const float4 rq = sh_rq[h];
        const float w  = sh_wo[h];
        a0 += w * tanh_approx(a + rq.x);
        a1 += w * tanh_approx(a + rq.y);
        a2 += w * tanh_approx(a + rq.z);
        a3 += w * tanh_approx(a + rq.w);
    }

    const float bo = __ldg(bo_p);
    const float m  = Maskp[b * CC + tid];
    float e0 = m * __expf(a0 + bo);
    float e1 = m * __expf(a1 + bo);
    float e2 = m * __expf(a2 + bo);
    float e3 = m * __expf(a3 + bo);

    // ---- softmax denominators (block reduce over 512) ----
    float s0 = e0, s1 = e1, s2 = e2, s3 = e3;
    #pragma unroll
    for (int off = 16; off > 0; off >>= 1) {
        s0 += __shfl_xor_sync(0xffffffffu, s0, off);
        s1 += __shfl_xor_sync(0xffffffffu, s1, off);
        s2 += __shfl_xor_sync(0xffffffffu, s2, off);
        s3 += __shfl_xor_sync(0xffffffffu, s3, off);
    }
    const int lane = tid & 31, wid = tid >> 5;
    if (lane == 0) {
        sh_part[0][wid] = s0; sh_part[1][wid] = s1;
        sh_part[2][wid] = s2; sh_part[3][wid] = s3;
    }
    __syncthreads();
    if (tid < 4) {
        float t = 0.f;
        #pragma unroll
        for (int i = 0; i < 16; i++) t += sh_part[tid][i];
        sh_tot[tid] = 1.f / (t + EPSF);
    }
    __syncthreads();

    float4 wv;
    wv.x = e0 * sh_tot[0];
    wv.y = e1 * sh_tot[1];
    wv.z = e2 * sh_tot[2];
    wv.w = e3 * sh_tot[3];
    sh_w[tid] = wv;

    // weights section of d_out (after output section)
    const int WOFF = BB * QQ * DD;
    out[WOFF + (b * QQ + q0 + 0) * CC + tid] = wv.x;
    out[WOFF + (b * QQ + q0 + 1) * CC + tid] = wv.y;
    out[WOFF + (b * QQ + q0 + 2) * CC + tid] = wv.z;
    out[WOFF + (b * QQ + q0 + 3) * CC + tid] = wv.w;
    __syncthreads();

    // ---- phase 2: output[q][d] = sum_c w[q][c] * ctx[b][c][d], d = tid ----
    float o0 = 0.f, o1 = 0.f, o2 = 0.f, o3 = 0.f;
    const float* cb = Ctx + (size_t)b * CC * DD + tid;
    #pragma unroll 4
    for (int c = 0; c < CC; c++) {
        const float v  = cb[(size_t)c * DD];
        const float4 w = sh_w[c];
        o0 += w.x * v;
        o1 += w.y * v;
        o2 += w.z * v;
        o3 += w.w * v;
    }
    out[(b * QQ + q0 + 0) * DD + tid] = o0;
    out[(b * QQ + q0 + 1) * DD + tid] = o1;
    out[(b * QQ + q0 + 2) * DD + tid] = o2;
    out[(b * QQ + q0 + 3) * DD + tid] = o3;
}

// ---------------------------------------------------------------------------
extern "C" void kernel_launch(void* const* d_in, const int* in_sizes, int n_in,
                              void* d_out, int out_size)
{
    const float* query   = (const float*)d_in[0];
    const float* context = (const float*)d_in[1];
    const float* mask    = (const float*)d_in[2];
    const float* W_c     = (const float*)d_in[3];
    const float* b_c     = (const float*)d_in[4];
    const float* W_q     = (const float*)d_in[5];
    const float* W_o     = (const float*)d_in[6];
    const float* b_o     = (const float*)d_in[7];
    float* out = (float*)d_out;

    fused_gemms<<<288, 256>>>(W_c, context, b_c, query, W_q);
    attn_main<<<BB * QQ / 4, 512>>>(context, mask, W_o, b_o, out);
}

// round 3
// speedup vs baseline: 1.7116x; 1.3244x over previous
#include <cuda_runtime.h>
#include <cuda_bf16.h>

// Problem constants
#define BB 8
#define QQ 64
#define CC 512
#define DD 512
#define HH 256
#define EPSF 1e-5f

__device__ float g_resq[BB * QQ * HH];        // [bq][h]
__device__ float g_rescT[BB * HH * CC];       // [b][h][c]

__device__ __forceinline__ float tanh_approx(float x) {
    float y;
    asm("tanh.approx.f32 %0, %1;" : "=f"(y) : "f"(x));
    return y;
}

// ---------------------------------------------------------------------------
// Fused GEMMs (unchanged from R2): 288 blocks, 64x64 TN tiles, double-buffered.
// ---------------------------------------------------------------------------
__global__ __launch_bounds__(256, 2)
void fused_gemms(const float* __restrict__ Wc,
                 const float* __restrict__ Ctx,
                 const float* __restrict__ bc,
                 const float* __restrict__ Qm,
                 const float* __restrict__ Wq)
{
    __shared__ float As[2][16][68];
    __shared__ float Bs[2][16][68];

    const int tid = threadIdx.x;
    const int tx  = tid & 15;
    const int ty  = tid >> 4;
    const int lr  = tid >> 2;
    const int ldg = tid & 3;

    const float *Ap, *Bp;
    const float* biasp = nullptr;
    float* outp;
    int ldo;

    const int blk = blockIdx.x;
    if (blk < 256) {
        const int b   = blk >> 5;
        const int rem = blk & 31;
        const int h0  = (rem >> 3) << 6;
        const int c0  = (rem & 7) << 6;
        Ap    = Wc + h0 * DD;
        Bp    = Ctx + ((size_t)b * CC + c0) * DD;
        outp  = g_rescT + (size_t)b * HH * CC + (size_t)h0 * CC + c0;
        ldo   = CC;
        biasp = bc + h0;
    } else {
        const int blk2 = blk - 256;
        const int m0   = (blk2 >> 2) << 6;
        const int n0   = (blk2 & 3) << 6;
        Ap   = Qm + m0 * DD;
        Bp   = Wq + n0 * DD;
        outp = g_resq + m0 * HH + n0;
        ldo  = HH;
    }

    const float* arow = Ap + lr * DD + ldg * 4;
    const float* brow = Bp + lr * DD + ldg * 4;

    float acc[4][4] = {};

    {
        float4 a4 = *(const float4*)arow;
        float4 b4 = *(const float4*)brow;
        const int d0 = ldg * 4;
        As[0][d0+0][lr] = a4.x; As[0][d0+1][lr] = a4.y;
        As[0][d0+2][lr] = a4.z; As[0][d0+3][lr] = a4.w;
        Bs[0][d0+0][lr] = b4.x; Bs[0][d0+1][lr] = b4.y;
        Bs[0][d0+2][lr] = b4.z; Bs[0][d0+3][lr] = b4.w;
    }
    __syncthreads();

    int buf = 0;
    for (int k0 = 16; k0 <= DD; k0 += 16) {
        float4 na, nb;
        const bool more = (k0 < DD);
        if (more) {
            na = *(const float4*)(arow + k0);
            nb = *(const float4*)(brow + k0);
        }

        #pragma unroll
        for (int d = 0; d < 16; d++) {
            float4 av = *(const float4*)&As[buf][d][ty * 4];
            float4 bv = *(const float4*)&Bs[buf][d][tx * 4];
            acc[0][0] += av.x * bv.x; acc[0][1] += av.x * bv.y;
            acc[0][2] += av.x * bv.z; acc[0][3] += av.x * bv.w;
            acc[1][0] += av.y * bv.x; acc[1][1] += av.y * bv.y;
            acc[1][2] += av.y * bv.z; acc[1][3] += av.y * bv.w;
            acc[2][0] += av.z * bv.x; acc[2][1] += av.z * bv.y;
            acc[2][2] += av.z * bv.z; acc[2][3] += av.z * bv.w;
            acc[3][0] += av.w * bv.x; acc[3][1] += av.w * bv.y;
            acc[3][2] += av.w * bv.z; acc[3][3] += av.w * bv.w;
        }

        if (more) {
            const int nbuf = buf ^ 1;
            const int d0 = ldg * 4;
            As[nbuf][d0+0][lr] = na.x; As[nbuf][d0+1][lr] = na.y;
            As[nbuf][d0+2][lr] = na.z; As[nbuf][d0+3][lr] = na.w;
            Bs[nbuf][d0+0][lr] = nb.x; Bs[nbuf][d0+1][lr] = nb.y;
            Bs[nbuf][d0+2][lr] = nb.z; Bs[nbuf][d0+3][lr] = nb.w;
        }
        __syncthreads();
        buf ^= 1;
    }

    #pragma unroll
    for (int i = 0; i < 4; i++) {
        const float bi = biasp ? biasp[ty * 4 + i] : 0.f;
        float4 o;
        o.x = acc[i][0] + bi; o.y = acc[i][1] + bi;
        o.z = acc[i][2] + bi; o.w = acc[i][3] + bi;
        *(float4*)(outp + (ty * 4 + i) * ldo + tx * 4) = o;
    }
}

// ---------------------------------------------------------------------------
// K3: 1024 threads/block, grid 128. Block = (b, 4 q's).
// Phase 1: half 0 covers h in [0,128), half 1 covers [128,256) -> combine in smem.
// Phase 2: half 0 covers c in [0,256), half 1 covers [256,512) -> combine in smem.
// Doubles resident warps (32/SM) with no extra L2 traffic.
// ---------------------------------------------------------------------------
__global__ __launch_bounds__(1024)
void attn_main(const float* __restrict__ Ctx,
               const float* __restrict__ Maskp,
               const float* __restrict__ Wo,
               const float* __restrict__ bo_p,
               float* __restrict__ out)
{
    const int blk  = blockIdx.x;       // 0..127
    const int b    = blk >> 4;
    const int q0   = (blk & 15) * 4;
    const int tid  = threadIdx.x;      // 0..1023
    const int c    = tid & 511;        // c in phase 1 / softmax, d in phase 2
    const int half = tid >> 9;         // 0 or 1

    __shared__ float4 sh_rq[HH];       // res_q for the 4 q's
    __shared__ float  sh_wo[HH];
    __shared__ float4 sh_acc[CC];      // cross-half partials (logits, then outputs)
    __shared__ float4 sh_w[CC];        // softmax weights for the 4 q's
    __shared__ float  sh_part[4][16];
    __shared__ float  sh_tot[4];

    if (tid < HH) {
        float4 r;
        r.x = g_resq[(b * QQ + q0 + 0) * HH + tid];
        r.y = g_resq[(b * QQ + q0 + 1) * HH + tid];
        r.z = g_resq[(b * QQ + q0 + 2) * HH + tid];
        r.w = g_resq[(b * QQ + q0 + 3) * HH + tid];
        sh_rq[tid] = r;
        sh_wo[tid] = Wo[tid];
    }
    __syncthreads();

    // ---- phase 1: partial logits over this half's h-range ----
    float a0 = 0.f, a1 = 0.f, a2 = 0.f, a3 = 0.f;
    {
        const int hbase = half << 7;   // 0 or 128
        const float* rc = g_rescT + (size_t)b * HH * CC + (size_t)hbase * CC + c;
        #pragma unroll 8
        for (int h = 0; h < 128; h++) {
            const float  a  = rc[(size_t)h * CC];
            const float4 rq = sh_rq[hbase + h];
            const float  w  = sh_wo[hbase + h];
            a0 += w * tanh_approx(a + rq.x);
            a1 += w * tanh_approx(a + rq.y);
            a2 += w * tanh_approx(a + rq.z);
            a3 += w * tanh_approx(a + rq.w);
        }
    }
    if (half == 0) {
        sh_acc[c] = make_float4(a0, a1, a2, a3);
    }
    __syncthreads();

    float e0, e1, e2, e3;
    if (half == 1) {
        const float4 p = sh_acc[c];
        const float bo = __ldg(bo_p);
        const float m  = Maskp[b * CC + c];
        e0 = m * __expf(a0 + p.x + bo);
        e1 = m * __expf(a1 + p.y + bo);
        e2 = m * __expf(a2 + p.z + bo);
        e3 = m * __expf(a3 + p.w + bo);

        float s0 = e0, s1 = e1, s2 = e2, s3 = e3;
        #pragma unroll
        for (int off = 16; off > 0; off >>= 1) {
            s0 += __shfl_xor_sync(0xffffffffu, s0, off);
            s1 += __shfl_xor_sync(0xffffffffu, s1, off);
            s2 += __shfl_xor_sync(0xffffffffu, s2, off);
            s3 += __shfl_xor_sync(0xffffffffu, s3, off);
        }
        const int lane = tid & 31, w2 = (tid >> 5) & 15;
        if (lane == 0) {
            sh_part[0][w2] = s0; sh_part[1][w2] = s1;
            sh_part[2][w2] = s2; sh_part[3][w2] = s3;
        }
    }
    __syncthreads();
    if (tid < 4) {
        float t = 0.f;
        #pragma unroll
        for (int i = 0; i < 16; i++) t += sh_part[tid][i];
        sh_tot[tid] = 1.f / (t + EPSF);
    }
    __syncthreads();

    if (half == 1) {
        float4 wv;
        wv.x = e0 * sh_tot[0];
        wv.y = e1 * sh_tot[1];
        wv.z = e2 * sh_tot[2];
        wv.w = e3 * sh_tot[3];
        sh_w[c] = wv;

        const int WOFF = BB * QQ * DD;
        out[WOFF + (b * QQ + q0 + 0) * CC + c] = wv.x;
        out[WOFF + (b * QQ + q0 + 1) * CC + c] = wv.y;
        out[WOFF + (b * QQ + q0 + 2) * CC + c] = wv.z;
        out[WOFF + (b * QQ + q0 + 3) * CC + c] = wv.w;
    }
    __syncthreads();

    // ---- phase 2: out[q][d] = sum_c w[q][c]*ctx[b][c][d]; split c by half ----
    float o0 = 0.f, o1 = 0.f, o2 = 0.f, o3 = 0.f;
    {
        const int cbase = half << 8;   // 0 or 256
        const float* cb = Ctx + (size_t)b * CC * DD + (size_t)cbase * DD + c;
        #pragma unroll 8
        for (int cc = 0; cc < 256; cc++) {
            const float  v = cb[(size_t)cc * DD];
            const float4 w = sh_w[cbase + cc];
            o0 += w.x * v;
            o1 += w.y * v;
            o2 += w.z * v;
            o3 += w.w * v;
        }
    }
    if (half == 0) {
        sh_acc[c] = make_float4(o0, o1, o2, o3);
    }
    __syncthreads();
    if (half == 1) {
        const float4 p = sh_acc[c];
        out[(b * QQ + q0 + 0) * DD + c] = o0 + p.x;
        out[(b * QQ + q0 + 1) * DD + c] = o1 + p.y;
        out[(b * QQ + q0 + 2) * DD + c] = o2 + p.z;
        out[(b * QQ + q0 + 3) * DD + c] = o3 + p.w;
    }
}

// ---------------------------------------------------------------------------
extern "C" void kernel_launch(void* const* d_in, const int* in_sizes, int n_in,
                              void* d_out, int out_size)
{
    const float* query   = (const float*)d_in[0];
    const float* context = (const float*)d_in[1];
    const float* mask    = (const float*)d_in[2];
    const float* W_c     = (const float*)d_in[3];
    const float* b_c     = (const float*)d_in[4];
    const float* W_q     = (const float*)d_in[5];
    const float* W_o     = (const float*)d_in[6];
    const float* b_o     = (const float*)d_in[7];
    float* out = (float*)d_out;

    fused_gemms<<<288, 256>>>(W_c, context, b_c, query, W_q);
    attn_main<<<BB * QQ / 4, 1024>>>(context, mask, W_o, b_o, out);
}

// round 4
// speedup vs baseline: 1.7538x; 1.0246x over previous
#include <cuda_runtime.h>
#include <cuda_bf16.h>

// Problem constants
#define BB 8
#define QQ 64
#define CC 512
#define DD 512
#define HH 256
#define EPSF 1e-5f
#define WOFF (BB * QQ * DD)

typedef unsigned long long ull;

__device__ float g_resq[BB * QQ * HH];        // [bq][h]
__device__ float g_rescT[BB * HH * CC];       // [b][h][c]

__device__ __forceinline__ float tanh_approx(float x) {
    float y;
    asm("tanh.approx.f32 %0, %1;" : "=f"(y) : "f"(x));
    return y;
}
__device__ __forceinline__ ull pack2(float x) {
    ull r; asm("mov.b64 %0, {%1, %1};" : "=l"(r) : "f"(x)); return r;
}
__device__ __forceinline__ void fma2(ull& d, ull a, ull b) {
    asm("fma.rn.f32x2 %0, %1, %2, %0;" : "+l"(d) : "l"(a), "l"(b));
}
__device__ __forceinline__ float2 unpack2(ull v) {
    float2 r; asm("mov.b64 {%0, %1}, %2;" : "=f"(r.x), "=f"(r.y) : "l"(v)); return r;
}

// ---------------------------------------------------------------------------
// A: Fused GEMMs with packed f32x2 FMA. 288 blocks, 64x64 TN tiles, K=512,
// double-buffered smem, float4 loads.
// ---------------------------------------------------------------------------
__global__ __launch_bounds__(256, 2)
void fused_gemms(const float* __restrict__ Wc,
                 const float* __restrict__ Ctx,
                 const float* __restrict__ bc,
                 const float* __restrict__ Qm,
                 const float* __restrict__ Wq)
{
    __shared__ float As[2][16][68];
    __shared__ float Bs[2][16][68];

    const int tid = threadIdx.x;
    const int tx  = tid & 15;
    const int ty  = tid >> 4;
    const int lr  = tid >> 2;
    const int ldg = tid & 3;

    const float *Ap, *Bp;
    const float* biasp = nullptr;
    float* outp;
    int ldo;

    const int blk = blockIdx.x;
    if (blk < 256) {
        const int b   = blk >> 5;
        const int rem = blk & 31;
        const int h0  = (rem >> 3) << 6;
        const int c0  = (rem & 7) << 6;
        Ap    = Wc + h0 * DD;
        Bp    = Ctx + ((size_t)b * CC + c0) * DD;
        outp  = g_rescT + (size_t)b * HH * CC + (size_t)h0 * CC + c0;
        ldo   = CC;
        biasp = bc + h0;
    } else {
        const int blk2 = blk - 256;
        const int m0   = (blk2 >> 2) << 6;
        const int n0   = (blk2 & 3) << 6;
        Ap   = Qm + m0 * DD;
        Bp   = Wq + n0 * DD;
        outp = g_resq + m0 * HH + n0;
        ldo  = HH;
    }

    const float* arow = Ap + lr * DD + ldg * 4;
    const float* brow = Bp + lr * DD + ldg * 4;

    ull acc[4][2] = {};

    {
        float4 a4 = *(const float4*)arow;
        float4 b4 = *(const float4*)brow;
        const int d0 = ldg * 4;
        As[0][d0+0][lr] = a4.x; As[0][d0+1][lr] = a4.y;
        As[0][d0+2][lr] = a4.z; As[0][d0+3][lr] = a4.w;
        Bs[0][d0+0][lr] = b4.x; Bs[0][d0+1][lr] = b4.y;
        Bs[0][d0+2][lr] = b4.z; Bs[0][d0+3][lr] = b4.w;
    }
    __syncthreads();

    int buf = 0;
    for (int k0 = 16; k0 <= DD; k0 += 16) {
        float4 na, nb;
        const bool more = (k0 < DD);
        if (more) {
            na = *(const float4*)(arow + k0);
            nb = *(const float4*)(brow + k0);
        }

        #pragma unroll
        for (int d = 0; d < 16; d++) {
            float4 av = *(const float4*)&As[buf][d][ty * 4];
            ulonglong2 bv = *(const ulonglong2*)&Bs[buf][d][tx * 4];
            ull a0 = pack2(av.x), a1 = pack2(av.y);
            ull a2 = pack2(av.z), a3 = pack2(av.w);
            fma2(acc[0][0], a0, bv.x); fma2(acc[0][1], a0, bv.y);
            fma2(acc[1][0], a1, bv.x); fma2(acc[1][1], a1, bv.y);
            fma2(acc[2][0], a2, bv.x); fma2(acc[2][1], a2, bv.y);
            fma2(acc[3][0], a3, bv.x); fma2(acc[3][1], a3, bv.y);
        }

        if (more) {
            const int nbuf = buf ^ 1;
            const int d0 = ldg * 4;
            As[nbuf][d0+0][lr] = na.x; As[nbuf][d0+1][lr] = na.y;
            As[nbuf][d0+2][lr] = na.z; As[nbuf][d0+3][lr] = na.w;
            Bs[nbuf][d0+0][lr] = nb.x; Bs[nbuf][d0+1][lr] = nb.y;
            Bs[nbuf][d0+2][lr] = nb.z; Bs[nbuf][d0+3][lr] = nb.w;
        }
        __syncthreads();
        buf ^= 1;
    }

    #pragma unroll
    for (int i = 0; i < 4; i++) {
        const float bi = biasp ? biasp[ty * 4 + i] : 0.f;
        float2 p0 = unpack2(acc[i][0]);
        float2 p1 = unpack2(acc[i][1]);
        float4 o;
        o.x = p0.x + bi; o.y = p0.y + bi;
        o.z = p1.x + bi; o.w = p1.y + bi;
        *(float4*)(outp + (ty * 4 + i) * ldo + tx * 4) = o;
    }
}

// ---------------------------------------------------------------------------
// B: logits (tanh over H) + softmax; writes weights to out[WOFF..].
// 1024 threads, grid 128. h-range split across halves, combine in smem.
// ---------------------------------------------------------------------------
__global__ __launch_bounds__(1024)
void logits_softmax(const float* __restrict__ Maskp,
                    const float* __restrict__ Wo,
                    const float* __restrict__ bo_p,
                    float* __restrict__ out)
{
    const int blk  = blockIdx.x;       // 0..127
    const int b    = blk >> 4;
    const int q0   = (blk & 15) * 4;
    const int tid  = threadIdx.x;
    const int c    = tid & 511;
    const int half = tid >> 9;

    __shared__ float4 sh_rq[HH];
    __shared__ float  sh_wo[HH];
    __shared__ float4 sh_acc[CC];
    __shared__ float  sh_part[4][16];
    __shared__ float  sh_tot[4];

    if (tid < HH) {
        float4 r;
        r.x = g_resq[(b * QQ + q0 + 0) * HH + tid];
        r.y = g_resq[(b * QQ + q0 + 1) * HH + tid];
        r.z = g_resq[(b * QQ + q0 + 2) * HH + tid];
        r.w = g_resq[(b * QQ + q0 + 3) * HH + tid];
        sh_rq[tid] = r;
        sh_wo[tid] = Wo[tid];
    }
    __syncthreads();

    float a0 = 0.f, a1 = 0.f, a2 = 0.f, a3 = 0.f;
    {
        const int hbase = half << 7;
        const float* rc = g_rescT + (size_t)b * HH * CC + (size_t)hbase * CC + c;
        #pragma unroll 8
        for (int h = 0; h < 128; h++) {
            const float  a  = rc[(size_t)h * CC];
            const float4 rq = sh_rq[hbase + h];
            const float  w  = sh_wo[hbase + h];
            a0 += w * tanh_approx(a + rq.x);
            a1 += w * tanh_approx(a + rq.y);
            a2 += w * tanh_approx(a + rq.z);
            a3 += w * tanh_approx(a + rq.w);
        }
    }
    if (half == 0) {
        sh_acc[c] = make_float4(a0, a1, a2, a3);
    }
    __syncthreads();

    float e0, e1, e2, e3;
    if (half == 1) {
        const float4 p = sh_acc[c];
        const float bo = __ldg(bo_p);
        const float m  = Maskp[b * CC + c];
        e0 = m * __expf(a0 + p.x + bo);
        e1 = m * __expf(a1 + p.y + bo);
        e2 = m * __expf(a2 + p.z + bo);
        e3 = m * __expf(a3 + p.w + bo);

        float s0 = e0, s1 = e1, s2 = e2, s3 = e3;
        #pragma unroll
        for (int off = 16; off > 0; off >>= 1) {
            s0 += __shfl_xor_sync(0xffffffffu, s0, off);
            s1 += __shfl_xor_sync(0xffffffffu, s1, off);
            s2 += __shfl_xor_sync(0xffffffffu, s2, off);
            s3 += __shfl_xor_sync(0xffffffffu, s3, off);
        }
        const int lane = tid & 31, w2 = (tid >> 5) & 15;
        if (lane == 0) {
            sh_part[0][w2] = s0; sh_part[1][w2] = s1;
            sh_part[2][w2] = s2; sh_part[3][w2] = s3;
        }
    }
    __syncthreads();
    if (tid < 4) {
        float t = 0.f;
        #pragma unroll
        for (int i = 0; i < 16; i++) t += sh_part[tid][i];
        sh_tot[tid] = 1.f / (t + EPSF);
    }
    __syncthreads();

    if (half == 1) {
        out[WOFF + (b * QQ + q0 + 0) * CC + c] = e0 * sh_tot[0];
        out[WOFF + (b * QQ + q0 + 1) * CC + c] = e1 * sh_tot[1];
        out[WOFF + (b * QQ + q0 + 2) * CC + c] = e2 * sh_tot[2];
        out[WOFF + (b * QQ + q0 + 3) * CC + c] = e3 * sh_tot[3];
    }
}

// ---------------------------------------------------------------------------
// C: output[bq][d] = sum_c weights[bq][c] * ctx[b][c][d]
// Tiled GEMM: per block 64q x 32d, K=512, double-buffered, f32x2 FMA.
// grid = 8 b * 16 d-tiles = 128 blocks, 256 threads.
// ---------------------------------------------------------------------------
__global__ __launch_bounds__(256)
void out_gemm(const float* __restrict__ Ctx,
              const float* __restrict__ Wgt,   // = out + WOFF
              float* __restrict__ out)
{
    const int blk = blockIdx.x;        // 0..127
    const int b   = blk >> 4;
    const int d0  = (blk & 15) * 32;
    const int tid = threadIdx.x;
    const int ty  = tid >> 4;          // q group (4 rows)
    const int tx  = tid & 15;          // d pair

    __shared__ float Ws[2][16][68];    // [cc][q]
    __shared__ float Cs[2][16][34];    // [cc][d]

    const float* Wp = Wgt + (size_t)b * QQ * CC;
    const float* Cp = Ctx + (size_t)b * CC * DD;

    const int qr = tid >> 2;           // 0..63 (weights load row)
    const int cg = tid & 3;            // c-group of 4
    const int cl = tid >> 4;           // 0..15 (ctx load row)
    const int dl = (tid & 15) * 2;

    ull acc[4] = {};

    // prologue: k-tile 0
    {
        float4 w4 = *(const float4*)&Wp[qr * CC + cg * 4];
        Ws[0][cg*4+0][qr] = w4.x; Ws[0][cg*4+1][qr] = w4.y;
        Ws[0][cg*4+2][qr] = w4.z; Ws[0][cg*4+3][qr] = w4.w;
        float2 c2 = *(const float2*)&Cp[(size_t)cl * DD + d0 + dl];
        Cs[0][cl][dl] = c2.x; Cs[0][cl][dl+1] = c2.y;
    }
    __syncthreads();

    int buf = 0;
    for (int c0 = 16; c0 <= CC; c0 += 16) {
        float4 nw; float2 nc;
        const bool more = (c0 < CC);
        if (more) {
            nw = *(const float4*)&Wp[qr * CC + c0 + cg * 4];
            nc = *(const float2*)&Cp[(size_t)(c0 + cl) * DD + d0 + dl];
        }

        #pragma unroll
        for (int cc = 0; cc < 16; cc++) {
            float4 w4 = *(const float4*)&Ws[buf][cc][ty * 4];
            ull cv = *(const ull*)&Cs[buf][cc][tx * 2];
            fma2(acc[0], pack2(w4.x), cv);
            fma2(acc[1], pack2(w4.y), cv);
            fma2(acc[2], pack2(w4.z), cv);
            fma2(acc[3], pack2(w4.w), cv);
        }

        if (more) {
            const int nbuf = buf ^ 1;
            Ws[nbuf][cg*4+0][qr] = nw.x; Ws[nbuf][cg*4+1][qr] = nw.y;
            Ws[nbuf][cg*4+2][qr] = nw.z; Ws[nbuf][cg*4+3][qr] = nw.w;
            Cs[nbuf][cl][dl] = nc.x; Cs[nbuf][cl][dl+1] = nc.y;
        }
        __syncthreads();
        buf ^= 1;
    }

    #pragma unroll
    for (int i = 0; i < 4; i++) {
        float2 p = unpack2(acc[i]);
        const int q = ty * 4 + i;
        *(float2*)&out[(b * QQ + q) * DD + d0 + tx * 2] = p;
    }
}

// ---------------------------------------------------------------------------
extern "C" void kernel_launch(void* const* d_in, const int* in_sizes, int n_in,
                              void* d_out, int out_size)
{
    const float* query   = (const float*)d_in[0];
    const float* context = (const float*)d_in[1];
    const float* mask    = (const float*)d_in[2];
    const float* W_c     = (const float*)d_in[3];
    const float* b_c     = (const float*)d_in[4];
    const float* W_q     = (const float*)d_in[5];
    const float* W_o     = (const float*)d_in[6];
    const float* b_o     = (const float*)d_in[7];
    float* out = (float*)d_out;

    fused_gemms<<<288, 256>>>(W_c, context, b_c, query, W_q);
    logits_softmax<<<128, 1024>>>(mask, W_o, b_o, out);
    out_gemm<<<128, 256>>>(context, out + WOFF, out);
}

// round 5
// speedup vs baseline: 1.8073x; 1.0305x over previous
#include <cuda_runtime.h>
#include <cuda_bf16.h>

// Problem constants
#define BB 8
#define QQ 64
#define CC 512
#define DD 512
#define HH 256
#define EPSF 1e-5f
#define WOFF (BB * QQ * DD)

typedef unsigned long long ull;

__device__ float g_resq[BB * QQ * HH];        // [bq][h]
__device__ float g_rescT[BB * HH * CC];       // [b][h][c]

__device__ __forceinline__ float tanh_approx(float x) {
    float y;
    asm("tanh.approx.f32 %0, %1;" : "=f"(y) : "f"(x));
    return y;
}
__device__ __forceinline__ ull pack2(float x) {
    ull r; asm("mov.b64 %0, {%1, %1};" : "=l"(r) : "f"(x)); return r;
}
__device__ __forceinline__ void fma2(ull& d, ull a, ull b) {
    asm("fma.rn.f32x2 %0, %1, %2, %0;" : "+l"(d) : "l"(a), "l"(b));
}
__device__ __forceinline__ float2 unpack2(ull v) {
    float2 r; asm("mov.b64 {%0, %1}, %2;" : "=f"(r.x), "=f"(r.y) : "l"(v)); return r;
}

// ---------------------------------------------------------------------------
// A: Fused GEMMs. 288 blocks x 128 threads. 64x64 TN tiles, K=512.
// Thread tile: 8 M-rows x 4 N-cols; accumulators are f32x2 pairs over M
// (A operand loaded pre-packed from smem as ulonglong2 over adjacent rows).
// LDS per d-iter: 48B for 32 FMA (was 32B/16FMA) -> smem pressure halved.
// ---------------------------------------------------------------------------
__global__ __launch_bounds__(128, 4)
void fused_gemms(const float* __restrict__ Wc,
                 const float* __restrict__ Ctx,
                 const float* __restrict__ bc,
                 const float* __restrict__ Qm,
                 const float* __restrict__ Wq)
{
    __shared__ float As[2][16][68];   // [d][m-row]; 68-pad keeps 16B align (272B rows)
    __shared__ float Bs[2][16][68];   // [d][n-col]

    const int tid  = threadIdx.x;     // 0..127
    const int tx   = tid & 15;        // n group (4 cols)
    const int ty   = tid >> 4;        // m group (8 rows)
    const int lr   = tid >> 1;        // load row 0..63
    const int lh   = tid & 1;         // load half (8 floats each)

    const float *Ap, *Bp;
    const float* biasp = nullptr;
    float* outp;
    int ldo;

    const int blk = blockIdx.x;
    if (blk < 256) {
        const int b   = blk >> 5;
        const int rem = blk & 31;
        const int h0  = (rem >> 3) << 6;
        const int c0  = (rem & 7) << 6;
        Ap    = Wc + h0 * DD;
        Bp    = Ctx + ((size_t)b * CC + c0) * DD;
        outp  = g_rescT + (size_t)b * HH * CC + (size_t)h0 * CC + c0;
        ldo   = CC;
        biasp = bc + h0;
    } else {
        const int blk2 = blk - 256;
        const int m0   = (blk2 >> 2) << 6;
        const int n0   = (blk2 & 3) << 6;
        Ap   = Qm + m0 * DD;
        Bp   = Wq + n0 * DD;
        outp = g_resq + m0 * HH + n0;
        ldo  = HH;
    }

    const float* arow = Ap + lr * DD + lh * 8;
    const float* brow = Bp + lr * DD + lh * 8;

    ull acc[4][4] = {};   // [row-pair][col]

    // Prologue: stage 0 (each thread: 8 contiguous k-floats of one row)
    {
        float4 a0 = *(const float4*)(arow);
        float4 a1 = *(const float4*)(arow + 4);
        float4 b0 = *(const float4*)(brow);
        float4 b1 = *(const float4*)(brow + 4);
        const int d0 = lh * 8;
        As[0][d0+0][lr] = a0.x; As[0][d0+1][lr] = a0.y;
        As[0][d0+2][lr] = a0.z; As[0][d0+3][lr] = a0.w;
        As[0][d0+4][lr] = a1.x; As[0][d0+5][lr] = a1.y;
        As[0][d0+6][lr] = a1.z; As[0][d0+7][lr] = a1.w;
        Bs[0][d0+0][lr] = b0.x; Bs[0][d0+1][lr] = b0.y;
        Bs[0][d0+2][lr] = b0.z; Bs[0][d0+3][lr] = b0.w;
        Bs[0][d0+4][lr] = b1.x; Bs[0][d0+5][lr] = b1.y;
        Bs[0][d0+6][lr] = b1.z; Bs[0][d0+7][lr] = b1.w;
    }
    __syncthreads();

    int buf = 0;
    for (int k0 = 16; k0 <= DD; k0 += 16) {
        float4 na0, na1, nb0, nb1;
        const bool more = (k0 < DD);
        if (more) {
            na0 = *(const float4*)(arow + k0);
            na1 = *(const float4*)(arow + k0 + 4);
            nb0 = *(const float4*)(brow + k0);
            nb1 = *(const float4*)(brow + k0 + 4);
        }

        #pragma unroll
        for (int d = 0; d < 16; d++) {
            // A: 8 rows as 4 packed f32x2 (adjacent rows) — no pack needed
            ulonglong2 am0 = *(const ulonglong2*)&As[buf][d][ty * 8];
            ulonglong2 am1 = *(const ulonglong2*)&As[buf][d][ty * 8 + 4];
            // B: 4 scalars, broadcast-packed
            float4 bv = *(const float4*)&Bs[buf][d][tx * 4];
            ull b0 = pack2(bv.x), b1 = pack2(bv.y);
            ull b2 = pack2(bv.z), b3 = pack2(bv.w);
            fma2(acc[0][0], am0.x, b0); fma2(acc[0][1], am0.x, b1);
            fma2(acc[0][2], am0.x, b2); fma2(acc[0][3], am0.x, b3);
            fma2(acc[1][0], am0.y, b0); fma2(acc[1][1], am0.y, b1);
            fma2(acc[1][2], am0.y, b2); fma2(acc[1][3], am0.y, b3);
            fma2(acc[2][0], am1.x, b0); fma2(acc[2][1], am1.x, b1);
            fma2(acc[2][2], am1.x, b2); fma2(acc[2][3], am1.x, b3);
            fma2(acc[3][0], am1.y, b0); fma2(acc[3][1], am1.y, b1);
            fma2(acc[3][2], am1.y, b2); fma2(acc[3][3], am1.y, b3);
        }

        if (more) {
            const int nbuf = buf ^ 1;
            const int d0 = lh * 8;
            As[nbuf][d0+0][lr] = na0.x; As[nbuf][d0+1][lr] = na0.y;
            As[nbuf][d0+2][lr] = na0.z; As[nbuf][d0+3][lr] = na0.w;
            As[nbuf][d0+4][lr] = na1.x; As[nbuf][d0+5][lr] = na1.y;
            As[nbuf][d0+6][lr] = na1.z; As[nbuf][d0+7][lr] = na1.w;
            Bs[nbuf][d0+0][lr] = nb0.x; Bs[nbuf][d0+1][lr] = nb0.y;
            Bs[nbuf][d0+2][lr] = nb0.z; Bs[nbuf][d0+3][lr] = nb0.w;
            Bs[nbuf][d0+4][lr] = nb1.x; Bs[nbuf][d0+5][lr] = nb1.y;
            Bs[nbuf][d0+6][lr] = nb1.z; Bs[nbuf][d0+7][lr] = nb1.w;
        }
        __syncthreads();
        buf ^= 1;
    }

    // Epilogue: acc[p][j] holds rows (ty*8 + 2p, +1), col tx*4+j
    #pragma unroll
    for (int p = 0; p < 4; p++) {
        const int r0 = ty * 8 + 2 * p;
        float bi0 = 0.f, bi1 = 0.f;
        if (biasp) { bi0 = biasp[r0]; bi1 = biasp[r0 + 1]; }
        float2 c0 = unpack2(acc[p][0]);
        float2 c1 = unpack2(acc[p][1]);
        float2 c2 = unpack2(acc[p][2]);
        float2 c3 = unpack2(acc[p][3]);
        float4 o0, o1;
        o0.x = c0.x + bi0; o0.y = c1.x + bi0; o0.z = c2.x + bi0; o0.w = c3.x + bi0;
        o1.x = c0.y + bi1; o1.y = c1.y + bi1; o1.z = c2.y + bi1; o1.w = c3.y + bi1;
        *(float4*)(outp + (size_t)r0 * ldo + tx * 4)       = o0;
        *(float4*)(outp + (size_t)(r0 + 1) * ldo + tx * 4) = o1;
    }
}

// ---------------------------------------------------------------------------
// B: logits (tanh over H) + softmax; writes weights to out[WOFF..].
// 1024 threads, grid 128. h-range split across halves, combine in smem.
// ---------------------------------------------------------------------------
__global__ __launch_bounds__(1024)
void logits_softmax(const float* __restrict__ Maskp,
                    const float* __restrict__ Wo,
                    const float* __restrict__ bo_p,
                    float* __restrict__ out)
{
    const int blk  = blockIdx.x;       // 0..127
    const int b    = blk >> 4;
    const int q0   = (blk & 15) * 4;
    const int tid  = threadIdx.x;
    const int c    = tid & 511;
    const int half = tid >> 9;

    __shared__ float4 sh_rq[HH];
    __shared__ float  sh_wo[HH];
    __shared__ float4 sh_acc[CC];
    __shared__ float  sh_part[4][16];
    __shared__ float  sh_tot[4];

    if (tid < HH) {
        float4 r;
        r.x = g_resq[(b * QQ + q0 + 0) * HH + tid];
        r.y = g_resq[(b * QQ + q0 + 1) * HH + tid];
        r.z = g_resq[(b * QQ + q0 + 2) * HH + tid];
        r.w = g_resq[(b * QQ + q0 + 3) * HH + tid];
        sh_rq[tid] = r;
        sh_wo[tid] = Wo[tid];
    }
    __syncthreads();

    float a0 = 0.f, a1 = 0.f, a2 = 0.f, a3 = 0.f;
    {
        const int hbase = half << 7;
        const float* rc = g_rescT + (size_t)b * HH * CC + (size_t)hbase * CC + c;
        #pragma unroll 8
        for (int h = 0; h < 128; h++) {
            const float  a  = rc[(size_t)h * CC];
            const float4 rq = sh_rq[hbase + h];
            const float  w  = sh_wo[hbase + h];
            a0 += w * tanh_approx(a + rq.x);
            a1 += w * tanh_approx(a + rq.y);
            a2 += w * tanh_approx(a + rq.z);
            a3 += w * tanh_approx(a + rq.w);
        }
    }
    if (half == 0) {
        sh_acc[c] = make_float4(a0, a1, a2, a3);
    }
    __syncthreads();

    float e0, e1, e2, e3;
    if (half == 1) {
        const float4 p = sh_acc[c];
        const float bo = __ldg(bo_p);
        const float m  = Maskp[b * CC + c];
        e0 = m * __expf(a0 + p.x + bo);
        e1 = m * __expf(a1 + p.y + bo);
        e2 = m * __expf(a2 + p.z + bo);
        e3 = m * __expf(a3 + p.w + bo);

        float s0 = e0, s1 = e1, s2 = e2, s3 = e3;
        #pragma unroll
        for (int off = 16; off > 0; off >>= 1) {
            s0 += __shfl_xor_sync(0xffffffffu, s0, off);
            s1 += __shfl_xor_sync(0xffffffffu, s1, off);
            s2 += __shfl_xor_sync(0xffffffffu, s2, off);
            s3 += __shfl_xor_sync(0xffffffffu, s3, off);
        }
        const int lane = tid & 31, w2 = (tid >> 5) & 15;
        if (lane == 0) {
            sh_part[0][w2] = s0; sh_part[1][w2] = s1;
            sh_part[2][w2] = s2; sh_part[3][w2] = s3;
        }
    }
    __syncthreads();
    if (tid < 4) {
        float t = 0.f;
        #pragma unroll
        for (int i = 0; i < 16; i++) t += sh_part[tid][i];
        sh_tot[tid] = 1.f / (t + EPSF);
    }
    __syncthreads();

    if (half == 1) {
        out[WOFF + (b * QQ + q0 + 0) * CC + c] = e0 * sh_tot[0];
        out[WOFF + (b * QQ + q0 + 1) * CC + c] = e1 * sh_tot[1];
        out[WOFF + (b * QQ + q0 + 2) * CC + c] = e2 * sh_tot[2];
        out[WOFF + (b * QQ + q0 + 3) * CC + c] = e3 * sh_tot[3];
    }
}

// ---------------------------------------------------------------------------
// C: output[bq][d] = sum_c weights[bq][c] * ctx[b][c][d]
// Tiled GEMM: per block 64q x 32d, K=512, double-buffered, f32x2 FMA.
// grid = 8 b * 16 d-tiles = 128 blocks, 256 threads.
// ---------------------------------------------------------------------------
__global__ __launch_bounds__(256)
void out_gemm(const float* __restrict__ Ctx,
              const float* __restrict__ Wgt,   // = out + WOFF
              float* __restrict__ out)
{
    const int blk = blockIdx.x;        // 0..127
    const int b   = blk >> 4;
    const int d0  = (blk & 15) * 32;
    const int tid = threadIdx.x;
    const int ty  = tid >> 4;          // q group (4 rows)
    const int tx  = tid & 15;          // d pair

    __shared__ float Ws[2][16][68];    // [cc][q]
    __shared__ float Cs[2][16][34];    // [cc][d]

    const float* Wp = Wgt + (size_t)b * QQ * CC;
    const float* Cp = Ctx + (size_t)b * CC * DD;

    const int qr = tid >> 2;           // 0..63 (weights load row)
    const int cg = tid & 3;            // c-group of 4
    const int cl = tid >> 4;           // 0..15 (ctx load row)
    const int dl = (tid & 15) * 2;

    ull acc[4] = {};

    {
        float4 w4 = *(const float4*)&Wp[qr * CC + cg * 4];
        Ws[0][cg*4+0][qr] = w4.x; Ws[0][cg*4+1][qr] = w4.y;
        Ws[0][cg*4+2][qr] = w4.z; Ws[0][cg*4+3][qr] = w4.w;
        float2 c2 = *(const float2*)&Cp[(size_t)cl * DD + d0 + dl];
        Cs[0][cl][dl] = c2.x; Cs[0][cl][dl+1] = c2.y;
    }
    __syncthreads();

    int buf = 0;
    for (int c0 = 16; c0 <= CC; c0 += 16) {
        float4 nw; float2 nc;
        const bool more = (c0 < CC);
        if (more) {
            nw = *(const float4*)&Wp[qr * CC + c0 + cg * 4];
            nc = *(const float2*)&Cp[(size_t)(c0 + cl) * DD + d0 + dl];
        }

        #pragma unroll
        for (int cc = 0; cc < 16; cc++) {
            float4 w4 = *(const float4*)&Ws[buf][cc][ty * 4];
            ull cv = *(const ull*)&Cs[buf][cc][tx * 2];
            fma2(acc[0], pack2(w4.x), cv);
            fma2(acc[1], pack2(w4.y), cv);
            fma2(acc[2], pack2(w4.z), cv);
            fma2(acc[3], pack2(w4.w), cv);
        }

        if (more) {
            const int nbuf = buf ^ 1;
            Ws[nbuf][cg*4+0][qr] = nw.x; Ws[nbuf][cg*4+1][qr] = nw.y;
            Ws[nbuf][cg*4+2][qr] = nw.z; Ws[nbuf][cg*4+3][qr] = nw.w;
            Cs[nbuf][cl][dl] = nc.x; Cs[nbuf][cl][dl+1] = nc.y;
        }
        __syncthreads();
        buf ^= 1;
    }

    #pragma unroll
    for (int i = 0; i < 4; i++) {
        float2 p = unpack2(acc[i]);
        const int q = ty * 4 + i;
        *(float2*)&out[(b * QQ + q) * DD + d0 + tx * 2] = p;
    }
}

// ---------------------------------------------------------------------------
extern "C" void kernel_launch(void* const* d_in, const int* in_sizes, int n_in,
                              void* d_out, int out_size)
{
    const float* query   = (const float*)d_in[0];
    const float* context = (const float*)d_in[1];
    const float* mask    = (const float*)d_in[2];
    const float* W_c     = (const float*)d_in[3];
    const float* b_c     = (const float*)d_in[4];
    const float* W_q     = (const float*)d_in[5];
    const float* W_o     = (const float*)d_in[6];
    const float* b_o     = (const float*)d_in[7];
    float* out = (float*)d_out;

    fused_gemms<<<288, 128>>>(W_c, context, b_c, query, W_q);
    logits_softmax<<<128, 1024>>>(mask, W_o, b_o, out);
    out_gemm<<<128, 256>>>(context, out + WOFF, out);
}

// round 7
// speedup vs baseline: 2.1462x; 1.1875x over previous
#include <cuda_runtime.h>
#include <cuda_bf16.h>
#include <cstdint>

// Problem constants
#define BB 8
#define QQ 64
#define CC 512
#define DD 512
#define HH 256
#define EPSF 1e-5f
#define WOFF (BB * QQ * DD)

typedef unsigned long long ull;

__device__ float g_resq[BB * QQ * HH];        // [bq][h]
__device__ float g_rescT[BB * HH * CC];       // [b][h][c]

__device__ __forceinline__ float tanh_approx(float x) {
    float y;
    asm("tanh.approx.f32 %0, %1;" : "=f"(y) : "f"(x));
    return y;
}
__device__ __forceinline__ ull pack2(float x) {
    ull r; asm("mov.b64 %0, {%1, %1};" : "=l"(r) : "f"(x)); return r;
}
__device__ __forceinline__ void fma2(ull& d, ull a, ull b) {
    asm("fma.rn.f32x2 %0, %1, %2, %0;" : "+l"(d) : "l"(a), "l"(b));
}
__device__ __forceinline__ float2 unpack2(ull v) {
    float2 r; asm("mov.b64 {%0, %1}, %2;" : "=f"(r.x), "=f"(r.y) : "l"(v)); return r;
}
__device__ __forceinline__ uint32_t cvt_tf32(float x) {
    uint32_t r; asm("cvt.rna.tf32.f32 %0, %1;" : "=r"(r) : "f"(x)); return r;
}
__device__ __forceinline__ uint32_t s2u(const void* p) {
    uint32_t a;
    asm("{ .reg .u64 t; cvta.to.shared.u64 t, %1; cvt.u32.u64 %0, t; }"
        : "=r"(a) : "l"(p));
    return a;
}

#define MMA_TF32(c, a, b0, b1)                                            \
    asm volatile("mma.sync.aligned.m16n8k8.row.col.f32.tf32.tf32.f32 "    \
                 "{%0,%1,%2,%3}, {%4,%5,%6,%7}, {%8,%9}, {%0,%1,%2,%3};"  \
                 : "+f"((c)[0]), "+f"((c)[1]), "+f"((c)[2]), "+f"((c)[3]) \
                 : "r"((a)[0]), "r"((a)[1]), "r"((a)[2]), "r"((a)[3]),    \
                   "r"(b0), "r"(b1))

#define LDA 36                     // padded row (conflict-free frag LDS: 4g+t4)
#define TILE_U (128 * LDA)         // uint32 per A or B buffer = 4608
#define TCG_SMEM (4 * TILE_U * 4)  // 2 bufs x (A+B) x 4B = 73728

// ---------------------------------------------------------------------------
// A: tf32 mma.sync GEMMs (HMMA tensor path; compute_103-safe).
//   blocks [0,64):  res_cT[b]: D[m=h(128)][n=c(128)] = Wc[h,:]·ctx[b][c,:] + bias
//   blocks [64,72): res_q:     D[m=bq(128)][n=h(128)] = q[bq,:]·Wq[h,:]
// Block 128x128, K=512 in 16 K-tiles of 32, double-buffered smem.
// 8 warps, warp tile 32m x 64n = 2x8 m16n8k8 tiles.
// ---------------------------------------------------------------------------
__global__ __launch_bounds__(256, 1)
void tc_gemms(const float* __restrict__ Wc,
              const float* __restrict__ Ctx,
              const float* __restrict__ bc,
              const float* __restrict__ Qm,
              const float* __restrict__ Wq)
{
    extern __shared__ uint32_t smem[];   // [buf][A|B][128][36]

    const int tid  = threadIdx.x;
    const int wid  = tid >> 5;
    const int lane = tid & 31;
    const int g    = lane >> 2;          // fragment group (row)
    const int tg   = lane & 3;           // thread-in-group (col)

    const int mbase = (wid & 3) * 32;    // warp rows
    const int nbase = (wid >> 2) * 64;   // warp cols

    // Block role
    const float *Ap, *Bp;
    const float* biasp = nullptr;
    float* outp;
    int ldo;
    const int blk = blockIdx.x;
    if (blk < 64) {
        const int b  = blk >> 3;
        const int ht = (blk >> 2) & 1;
        const int ct = blk & 3;
        Ap    = Wc + (size_t)(ht * 128) * DD;
        Bp    = Ctx + (size_t)b * CC * DD + (size_t)(ct * 128) * DD;
        outp  = g_rescT + (size_t)b * HH * CC + (size_t)(ht * 128) * CC + ct * 128;
        ldo   = CC;
        biasp = bc + ht * 128;
    } else {
        const int blk2 = blk - 64;
        const int mt = blk2 >> 1;
        const int nt = blk2 & 1;
        Ap   = Qm + (size_t)(mt * 128) * DD;
        Bp   = Wq + (size_t)(nt * 128) * DD;
        outp = g_resq + (size_t)(mt * 128) * HH + nt * 128;
        ldo  = HH;
    }

    float acc[2][8][4] = {};
    float4 ra[4], rb[4];

    // per-thread staging coordinates (4 float4 each for A and B per K-tile)
    int sm[4], sk[4];
    #pragma unroll
    for (int i = 0; i < 4; i++) {
        const int f = tid + (i << 8);    // 0..1023
        sm[i] = f >> 3;                  // row 0..127
        sk[i] = (f & 7) << 2;            // k offset 0,4,..,28
    }

    auto ldg_tile = [&](int kt) {
        #pragma unroll
        for (int i = 0; i < 4; i++) {
            ra[i] = *(const float4*)(Ap + (size_t)sm[i] * DD + kt + sk[i]);
            rb[i] = *(const float4*)(Bp + (size_t)sm[i] * DD + kt + sk[i]);
        }
    };
    auto sts_tile = [&](int buf) {
        uint32_t* A_s = smem + buf * (2 * TILE_U);
        uint32_t* B_s = A_s + TILE_U;
        #pragma unroll
        for (int i = 0; i < 4; i++) {
            uint32_t aa = s2u(A_s + sm[i] * LDA + sk[i]);
            asm volatile("st.shared.v4.b32 [%0], {%1,%2,%3,%4};"
                         :: "r"(aa), "r"(cvt_tf32(ra[i].x)), "r"(cvt_tf32(ra[i].y)),
                            "r"(cvt_tf32(ra[i].z)), "r"(cvt_tf32(ra[i].w)) : "memory");
            uint32_t ba = s2u(B_s + sm[i] * LDA + sk[i]);
            asm volatile("st.shared.v4.b32 [%0], {%1,%2,%3,%4};"
                         :: "r"(ba), "r"(cvt_tf32(rb[i].x)), "r"(cvt_tf32(rb[i].y)),
                            "r"(cvt_tf32(rb[i].z)), "r"(cvt_tf32(rb[i].w)) : "memory");
        }
    };

    ldg_tile(0);
    sts_tile(0);
    __syncthreads();

    #pragma unroll 1
    for (int t = 0; t < 16; t++) {
        const int buf = t & 1;
        if (t < 15) ldg_tile((t + 1) * 32);

        const uint32_t* A_s = smem + buf * (2 * TILE_U);
        const uint32_t* B_s = A_s + TILE_U;
        #pragma unroll
        for (int ks = 0; ks < 4; ks++) {
            const int kc = ks * 8;
            uint32_t a[2][4];
            #pragma unroll
            for (int mt = 0; mt < 2; mt++) {
                const int rbase = (mbase + mt * 16 + g) * LDA + kc + tg;
                a[mt][0] = A_s[rbase];
                a[mt][1] = A_s[rbase + 8 * LDA];
                a[mt][2] = A_s[rbase + 4];
                a[mt][3] = A_s[rbase + 8 * LDA + 4];
            }
            #pragma unroll
            for (int nt = 0; nt < 8; nt++) {
                const int bbase = (nbase + nt * 8 + g) * LDA + kc + tg;
                const uint32_t b0 = B_s[bbase];
                const uint32_t b1 = B_s[bbase + 4];
                MMA_TF32(acc[0][nt], a[0], b0, b1);
                MMA_TF32(acc[1][nt], a[1], b0, b1);
            }
        }

        if (t < 15) sts_tile(buf ^ 1);
        __syncthreads();
    }

    // Epilogue
    #pragma unroll
    for (int mt = 0; mt < 2; mt++) {
        const int row0 = mbase + mt * 16 + g;
        const int row1 = row0 + 8;
        const float bi0 = biasp ? biasp[row0] : 0.f;
        const float bi1 = biasp ? biasp[row1] : 0.f;
        #pragma unroll
        for (int nt = 0; nt < 8; nt++) {
            const int col = nbase + nt * 8 + tg * 2;
            float2 o0; o0.x = acc[mt][nt][0] + bi0; o0.y = acc[mt][nt][1] + bi0;
            float2 o1; o1.x = acc[mt][nt][2] + bi1; o1.y = acc[mt][nt][3] + bi1;
            *(float2*)(outp + (size_t)row0 * ldo + col) = o0;
            *(float2*)(outp + (size_t)row1 * ldo + col) = o1;
        }
    }
}

// ---------------------------------------------------------------------------
// B: logits (tanh over H) + softmax; writes weights to out[WOFF..].
// 1024 threads, grid 128. h-range split across halves, combine in smem.
// ---------------------------------------------------------------------------
__global__ __launch_bounds__(1024)
void logits_softmax(const float* __restrict__ Maskp,
                    const float* __restrict__ Wo,
                    const float* __restrict__ bo_p,
                    float* __restrict__ out)
{
    const int blk  = blockIdx.x;       // 0..127
    const int b    = blk >> 4;
    const int q0   = (blk & 15) * 4;
    const int tid  = threadIdx.x;
    const int c    = tid & 511;
    const int half = tid >> 9;

    __shared__ float4 sh_rq[HH];
    __shared__ float  sh_wo[HH];
    __shared__ float4 sh_acc[CC];
    __shared__ float  sh_part[4][16];
    __shared__ float  sh_tot[4];

    if (tid < HH) {
        float4 r;
        r.x = g_resq[(b * QQ + q0 + 0) * HH + tid];
        r.y = g_resq[(b * QQ + q0 + 1) * HH + tid];
        r.z = g_resq[(b * QQ + q0 + 2) * HH + tid];
        r.w = g_resq[(b * QQ + q0 + 3) * HH + tid];
        sh_rq[tid] = r;
        sh_wo[tid] = Wo[tid];
    }
    __syncthreads();

    float a0 = 0.f, a1 = 0.f, a2 = 0.f, a3 = 0.f;
    {
        const int hbase = half << 7;
        const float* rc = g_rescT + (size_t)b * HH * CC + (size_t)hbase * CC + c;
        #pragma unroll 8
        for (int h = 0; h < 128; h++) {
            const float  a  = rc[(size_t)h * CC];
            const float4 rq = sh_rq[hbase + h];
            const float  w  = sh_wo[hbase + h];
            a0 += w * tanh_approx(a + rq.x);
            a1 += w * tanh_approx(a + rq.y);
            a2 += w * tanh_approx(a + rq.z);
            a3 += w * tanh_approx(a + rq.w);
        }
    }
    if (half == 0) {
        sh_acc[c] = make_float4(a0, a1, a2, a3);
    }
    __syncthreads();

    float e0, e1, e2, e3;
    if (half == 1) {
        const float4 p = sh_acc[c];
        const float bo = __ldg(bo_p);
        const float m  = Maskp[b * CC + c];
        e0 = m * __expf(a0 + p.x + bo);
        e1 = m * __expf(a1 + p.y + bo);
        e2 = m * __expf(a2 + p.z + bo);
        e3 = m * __expf(a3 + p.w + bo);

        float s0 = e0, s1 = e1, s2 = e2, s3 = e3;
        #pragma unroll
        for (int off = 16; off > 0; off >>= 1) {
            s0 += __shfl_xor_sync(0xffffffffu, s0, off);
            s1 += __shfl_xor_sync(0xffffffffu, s1, off);
            s2 += __shfl_xor_sync(0xffffffffu, s2, off);
            s3 += __shfl_xor_sync(0xffffffffu, s3, off);
        }
        const int lane = tid & 31, w2 = (tid >> 5) & 15;
        if (lane == 0) {
            sh_part[0][w2] = s0; sh_part[1][w2] = s1;
            sh_part[2][w2] = s2; sh_part[3][w2] = s3;
        }
    }
    __syncthreads();
    if (tid < 4) {
        float t = 0.f;
        #pragma unroll
        for (int i = 0; i < 16; i++) t += sh_part[tid][i];
        sh_tot[tid] = 1.f / (t + EPSF);
    }
    __syncthreads();

    if (half == 1) {
        out[WOFF + (b * QQ + q0 + 0) * CC + c] = e0 * sh_tot[0];
        out[WOFF + (b * QQ + q0 + 1) * CC + c] = e1 * sh_tot[1];
        out[WOFF + (b * QQ + q0 + 2) * CC + c] = e2 * sh_tot[2];
        out[WOFF + (b * QQ + q0 + 3) * CC + c] = e3 * sh_tot[3];
    }
}

// ---------------------------------------------------------------------------
// C: output[bq][d] = sum_c weights[bq][c] * ctx[b][c][d]
// Tiled GEMM: 64q x 32d per block, K=512, double-buffered, f32x2 FMA.
// ---------------------------------------------------------------------------
__global__ __launch_bounds__(256)
void out_gemm(const float* __restrict__ Ctx,
              const float* __restrict__ Wgt,
              float* __restrict__ out)
{
    const int blk = blockIdx.x;        // 0..127
    const int b   = blk >> 4;
    const int d0  = (blk & 15) * 32;
    const int tid = threadIdx.x;
    const int ty  = tid >> 4;
    const int tx  = tid & 15;

    __shared__ float Ws[2][16][68];
    __shared__ float Cs[2][16][34];

    const float* Wp = Wgt + (size_t)b * QQ * CC;
    const float* Cp = Ctx + (size_t)b * CC * DD;

    const int qr = tid >> 2;
    const int cg = tid & 3;
    const int cl = tid >> 4;
    const int dl = (tid & 15) * 2;

    ull acc[4] = {};

    {
        float4 w4 = *(const float4*)&Wp[qr * CC + cg * 4];
        Ws[0][cg*4+0][qr] = w4.x; Ws[0][cg*4+1][qr] = w4.y;
        Ws[0][cg*4+2][qr] = w4.z; Ws[0][cg*4+3][qr] = w4.w;
        float2 c2 = *(const float2*)&Cp[(size_t)cl * DD + d0 + dl];
        Cs[0][cl][dl] = c2.x; Cs[0][cl][dl+1] = c2.y;
    }
    __syncthreads();

    int buf = 0;
    for (int c0 = 16; c0 <= CC; c0 += 16) {
        float4 nw; float2 nc;
        const bool more = (c0 < CC);
        if (more) {
            nw = *(const float4*)&Wp[qr * CC + c0 + cg * 4];
            nc = *(const float2*)&Cp[(size_t)(c0 + cl) * DD + d0 + dl];
        }

        #pragma unroll
        for (int cc = 0; cc < 16; cc++) {
            float4 w4 = *(const float4*)&Ws[buf][cc][ty * 4];
            ull cv = *(const ull*)&Cs[buf][cc][tx * 2];
            fma2(acc[0], pack2(w4.x), cv);
            fma2(acc[1], pack2(w4.y), cv);
            fma2(acc[2], pack2(w4.z), cv);
            fma2(acc[3], pack2(w4.w), cv);
        }

        if (more) {
            const int nbuf = buf ^ 1;
            Ws[nbuf][cg*4+0][qr] = nw.x; Ws[nbuf][cg*4+1][qr] = nw.y;
            Ws[nbuf][cg*4+2][qr] = nw.z; Ws[nbuf][cg*4+3][qr] = nw.w;
            Cs[nbuf][cl][dl] = nc.x; Cs[nbuf][cl][dl+1] = nc.y;
        }
        __syncthreads();
        buf ^= 1;
    }

    #pragma unroll
    for (int i = 0; i < 4; i++) {
        float2 p = unpack2(acc[i]);
        const int q = ty * 4 + i;
        *(float2*)&out[(b * QQ + q) * DD + d0 + tx * 2] = p;
    }
}

// ---------------------------------------------------------------------------
extern "C" void kernel_launch(void* const* d_in, const int* in_sizes, int n_in,
                              void* d_out, int out_size)
{
    const float* query   = (const float*)d_in[0];
    const float* context = (const float*)d_in[1];
    const float* mask    = (const float*)d_in[2];
    const float* W_c     = (const float*)d_in[3];
    const float* b_c     = (const float*)d_in[4];
    const float* W_q     = (const float*)d_in[5];
    const float* W_o     = (const float*)d_in[6];
    const float* b_o     = (const float*)d_in[7];
    float* out = (float*)d_out;

    cudaFuncSetAttribute(tc_gemms, cudaFuncAttributeMaxDynamicSharedMemorySize,
                         TCG_SMEM);

    tc_gemms<<<72, 256, TCG_SMEM>>>(W_c, context, b_c, query, W_q);
    logits_softmax<<<128, 1024>>>(mask, W_o, b_o, out);
    out_gemm<<<128, 256>>>(context, out + WOFF, out);
}

// round 8
// speedup vs baseline: 2.2664x; 1.0560x over previous
#include <cuda_runtime.h>
#include <cuda_bf16.h>
#include <cstdint>

// Problem constants
#define BB 8
#define QQ 64
#define CC 512
#define DD 512
#define HH 256
#define EPSF 1e-5f
#define WOFF (BB * QQ * DD)

typedef unsigned long long ull;

__device__ float g_resq[BB * QQ * HH];        // [bq][h]
__device__ float g_rescT[BB * HH * CC];       // [b][h][c]

__device__ __forceinline__ float tanh_approx(float x) {
    float y;
    asm("tanh.approx.f32 %0, %1;" : "=f"(y) : "f"(x));
    return y;
}
__device__ __forceinline__ ull pack2(float x) {
    ull r; asm("mov.b64 %0, {%1, %1};" : "=l"(r) : "f"(x)); return r;
}
__device__ __forceinline__ void fma2(ull& d, ull a, ull b) {
    asm("fma.rn.f32x2 %0, %1, %2, %0;" : "+l"(d) : "l"(a), "l"(b));
}
__device__ __forceinline__ float2 unpack2(ull v) {
    float2 r; asm("mov.b64 {%0, %1}, %2;" : "=f"(r.x), "=f"(r.y) : "l"(v)); return r;
}
__device__ __forceinline__ uint32_t cvt_tf32(float x) {
    uint32_t r; asm("cvt.rna.tf32.f32 %0, %1;" : "=r"(r) : "f"(x)); return r;
}
__device__ __forceinline__ uint32_t s2u(const void* p) {
    uint32_t a;
    asm("{ .reg .u64 t; cvta.to.shared.u64 t, %1; cvt.u32.u64 %0, t; }"
        : "=r"(a) : "l"(p));
    return a;
}

#define MMA_TF32(c, a, b0, b1)                                            \
    asm volatile("mma.sync.aligned.m16n8k8.row.col.f32.tf32.tf32.f32 "    \
                 "{%0,%1,%2,%3}, {%4,%5,%6,%7}, {%8,%9}, {%0,%1,%2,%3};"  \
                 : "+f"((c)[0]), "+f"((c)[1]), "+f"((c)[2]), "+f"((c)[3]) \
                 : "r"((a)[0]), "r"((a)[1]), "r"((a)[2]), "r"((a)[3]),    \
                   "r"(b0), "r"(b1))

#define LDA 36                       // padded row (conflict-free frag LDS)
#define ATILE_U (128 * LDA)          // 4608 u32
#define BTILE_U (64 * LDA)           // 2304 u32
#define STAGE_U (ATILE_U + BTILE_U)  // 6912 u32
#define TCG_SMEM (2 * STAGE_U * 4)   // 55296 B

// ---------------------------------------------------------------------------
// A: tf32 mma.sync GEMMs. 144 blocks x 256 threads (fills 148 SMs).
//   blocks [0,128):  res_cT[b]: D[m=h(128)][n=c(64)] = Wc[h,:]·ctx[b][c,:]+bias
//   blocks [128,144): res_q:    D[m=bq(128)][n=h(64)] = q[bq,:]·Wq[h,:]
// Block 128x64, K=512 in 16 K-tiles of 32, double-buffered smem.
// 8 warps in 4x2; warp tile 32m x 32n = 2x4 m16n8k8 tiles.
// ---------------------------------------------------------------------------
__global__ __launch_bounds__(256, 2)
void tc_gemms(const float* __restrict__ Wc,
              const float* __restrict__ Ctx,
              const float* __restrict__ bc,
              const float* __restrict__ Qm,
              const float* __restrict__ Wq)
{
    extern __shared__ uint32_t smem[];   // [buf][ A 128x36 | B 64x36 ]

    const int tid  = threadIdx.x;
    const int wid  = tid >> 5;
    const int lane = tid & 31;
    const int g    = lane >> 2;          // fragment row group
    const int tg   = lane & 3;           // thread-in-group

    const int mbase = (wid & 3) * 32;    // warp rows (4 warps over M)
    const int nbase = (wid >> 2) * 32;   // warp cols (2 warps over N)

    // Block role
    const float *Ap, *Bp;
    const float* biasp = nullptr;
    float* outp;
    int ldo;
    const int blk = blockIdx.x;
    if (blk < 128) {
        const int b  = blk >> 4;
        const int ht = (blk >> 3) & 1;
        const int ct = blk & 7;
        Ap    = Wc + (size_t)(ht * 128) * DD;
        Bp    = Ctx + (size_t)b * CC * DD + (size_t)(ct * 64) * DD;
        outp  = g_rescT + (size_t)b * HH * CC + (size_t)(ht * 128) * CC + ct * 64;
        ldo   = CC;
        biasp = bc + ht * 128;
    } else {
        const int blk2 = blk - 128;      // 0..15
        const int mt = blk2 >> 2;        // 0..3
        const int nt = blk2 & 3;         // 0..3
        Ap   = Qm + (size_t)(mt * 128) * DD;
        Bp   = Wq + (size_t)(nt * 64) * DD;
        outp = g_resq + (size_t)(mt * 128) * HH + nt * 64;
        ldo  = HH;
    }

    float acc[2][4][4] = {};
    float4 ra[4], rb[2];

    // staging coords: A 1024 float4 (4/thread), B 512 float4 (2/thread)
    int am[4], ak[4], bm[2], bk[2];
    #pragma unroll
    for (int i = 0; i < 4; i++) {
        const int f = tid + (i << 8);
        am[i] = f >> 3;
        ak[i] = (f & 7) << 2;
    }
    #pragma unroll
    for (int i = 0; i < 2; i++) {
        const int f = tid + (i << 8);
        bm[i] = f >> 3;
        bk[i] = (f & 7) << 2;
    }

    auto ldg_tile = [&](int kt) {
        #pragma unroll
        for (int i = 0; i < 4; i++)
            ra[i] = *(const float4*)(Ap + (size_t)am[i] * DD + kt + ak[i]);
        #pragma unroll
        for (int i = 0; i < 2; i++)
            rb[i] = *(const float4*)(Bp + (size_t)bm[i] * DD + kt + bk[i]);
    };
    auto sts_tile = [&](int buf) {
        uint32_t* A_s = smem + buf * STAGE_U;
        uint32_t* B_s = A_s + ATILE_U;
        #pragma unroll
        for (int i = 0; i < 4; i++) {
            uint32_t aa = s2u(A_s + am[i] * LDA + ak[i]);
            asm volatile("st.shared.v4.b32 [%0], {%1,%2,%3,%4};"
                         :: "r"(aa), "r"(cvt_tf32(ra[i].x)), "r"(cvt_tf32(ra[i].y)),
                            "r"(cvt_tf32(ra[i].z)), "r"(cvt_tf32(ra[i].w)) : "memory");
        }
        #pragma unroll
        for (int i = 0; i < 2; i++) {
            uint32_t ba = s2u(B_s + bm[i] * LDA + bk[i]);
            asm volatile("st.shared.v4.b32 [%0], {%1,%2,%3,%4};"
                         :: "r"(ba), "r"(cvt_tf32(rb[i].x)), "r"(cvt_tf32(rb[i].y)),
                            "r"(cvt_tf32(rb[i].z)), "r"(cvt_tf32(rb[i].w)) : "memory");
        }
    };

    ldg_tile(0);
    sts_tile(0);
    __syncthreads();

    #pragma unroll 1
    for (int t = 0; t < 16; t++) {
        const int buf = t & 1;
        if (t < 15) ldg_tile((t + 1) * 32);

        const uint32_t* A_s = smem + buf * STAGE_U;
        const uint32_t* B_s = A_s + ATILE_U;
        #pragma unroll
        for (int ks = 0; ks < 4; ks++) {
            const int kc = ks * 8;
            uint32_t a[2][4];
            #pragma unroll
            for (int mt = 0; mt < 2; mt++) {
                const int rbase = (mbase + mt * 16 + g) * LDA + kc + tg;
                a[mt][0] = A_s[rbase];
                a[mt][1] = A_s[rbase + 8 * LDA];
                a[mt][2] = A_s[rbase + 4];
                a[mt][3] = A_s[rbase + 8 * LDA + 4];
            }
            #pragma unroll
            for (int nt = 0; nt < 4; nt++) {
                const int bbase = (nbase + nt * 8 + g) * LDA + kc + tg;
                const uint32_t b0 = B_s[bbase];
                const uint32_t b1 = B_s[bbase + 4];
                MMA_TF32(acc[0][nt], a[0], b0, b1);
                MMA_TF32(acc[1][nt], a[1], b0, b1);
            }
        }

        if (t < 15) sts_tile(buf ^ 1);
        __syncthreads();
    }

    // Epilogue
    #pragma unroll
    for (int mt = 0; mt < 2; mt++) {
        const int row0 = mbase + mt * 16 + g;
        const int row1 = row0 + 8;
        const float bi0 = biasp ? biasp[row0] : 0.f;
        const float bi1 = biasp ? biasp[row1] : 0.f;
        #pragma unroll
        for (int nt = 0; nt < 4; nt++) {
            const int col = nbase + nt * 8 + tg * 2;
            float2 o0; o0.x = acc[mt][nt][0] + bi0; o0.y = acc[mt][nt][1] + bi0;
            float2 o1; o1.x = acc[mt][nt][2] + bi1; o1.y = acc[mt][nt][3] + bi1;
            *(float2*)(outp + (size_t)row0 * ldo + col) = o0;
            *(float2*)(outp + (size_t)row1 * ldo + col) = o1;
        }
    }
}

// ---------------------------------------------------------------------------
// B: logits (tanh over H) + softmax; writes weights to out[WOFF..].
// 1024 threads, grid 128. h-range split across halves, combine in smem.
// ---------------------------------------------------------------------------
__global__ __launch_bounds__(1024)
void logits_softmax(const float* __restrict__ Maskp,
                    const float* __restrict__ Wo,
                    const float* __restrict__ bo_p,
                    float* __restrict__ out)
{
    const int blk  = blockIdx.x;       // 0..127
    const int b    = blk >> 4;
    const int q0   = (blk & 15) * 4;
    const int tid  = threadIdx.x;
    const int c    = tid & 511;
    const int half = tid >> 9;

    __shared__ float4 sh_rq[HH];
    __shared__ float  sh_wo[HH];
    __shared__ float4 sh_acc[CC];
    __shared__ float  sh_part[4][16];
    __shared__ float  sh_tot[4];

    if (tid < HH) {
        float4 r;
        r.x = g_resq[(b * QQ + q0 + 0) * HH + tid];
        r.y = g_resq[(b * QQ + q0 + 1) * HH + tid];
        r.z = g_resq[(b * QQ + q0 + 2) * HH + tid];
        r.w = g_resq[(b * QQ + q0 + 3) * HH + tid];
        sh_rq[tid] = r;
        sh_wo[tid] = Wo[tid];
    }
    __syncthreads();

    float a0 = 0.f, a1 = 0.f, a2 = 0.f, a3 = 0.f;
    {
        const int hbase = half << 7;
        const float* rc = g_rescT + (size_t)b * HH * CC + (size_t)hbase * CC + c;
        #pragma unroll 8
        for (int h = 0; h < 128; h++) {
            const float  a  = rc[(size_t)h * CC];
            const float4 rq = sh_rq[hbase + h];
            const float  w  = sh_wo[hbase + h];
            a0 += w * tanh_approx(a + rq.x);
            a1 += w * tanh_approx(a + rq.y);
            a2 += w * tanh_approx(a + rq.z);
            a3 += w * tanh_approx(a + rq.w);
        }
    }
    if (half == 0) {
        sh_acc[c] = make_float4(a0, a1, a2, a3);
    }
    __syncthreads();

    float e0, e1, e2, e3;
    if (half == 1) {
        const float4 p = sh_acc[c];
        const float bo = __ldg(bo_p);
        const float m  = Maskp[b * CC + c];
        e0 = m * __expf(a0 + p.x + bo);
        e1 = m * __expf(a1 + p.y + bo);
        e2 = m * __expf(a2 + p.z + bo);
        e3 = m * __expf(a3 + p.w + bo);

        float s0 = e0, s1 = e1, s2 = e2, s3 = e3;
        #pragma unroll
        for (int off = 16; off > 0; off >>= 1) {
            s0 += __shfl_xor_sync(0xffffffffu, s0, off);
            s1 += __shfl_xor_sync(0xffffffffu, s1, off);
            s2 += __shfl_xor_sync(0xffffffffu, s2, off);
            s3 += __shfl_xor_sync(0xffffffffu, s3, off);
        }
        const int lane = tid & 31, w2 = (tid >> 5) & 15;
        if (lane == 0) {
            sh_part[0][w2] = s0; sh_part[1][w2] = s1;
            sh_part[2][w2] = s2; sh_part[3][w2] = s3;
        }
    }
    __syncthreads();
    if (tid < 4) {
        float t = 0.f;
        #pragma unroll
        for (int i = 0; i < 16; i++) t += sh_part[tid][i];
        sh_tot[tid] = 1.f / (t + EPSF);
    }
    __syncthreads();

    if (half == 1) {
        out[WOFF + (b * QQ + q0 + 0) * CC + c] = e0 * sh_tot[0];
        out[WOFF + (b * QQ + q0 + 1) * CC + c] = e1 * sh_tot[1];
        out[WOFF + (b * QQ + q0 + 2) * CC + c] = e2 * sh_tot[2];
        out[WOFF + (b * QQ + q0 + 3) * CC + c] = e3 * sh_tot[3];
    }
}

// ---------------------------------------------------------------------------
// C: output[bq][d] = sum_c weights[bq][c] * ctx[b][c][d]
// Tiled GEMM: 64q x 32d per block, K=512, double-buffered, f32x2 FMA.
// ---------------------------------------------------------------------------
__global__ __launch_bounds__(256)
void out_gemm(const float* __restrict__ Ctx,
              const float* __restrict__ Wgt,
              float* __restrict__ out)
{
    const int blk = blockIdx.x;        // 0..127
    const int b   = blk >> 4;
    const int d0  = (blk & 15) * 32;
    const int tid = threadIdx.x;
    const int ty  = tid >> 4;
    const int tx  = tid & 15;

    __shared__ float Ws[2][16][68];
    __shared__ float Cs[2][16][34];

    const float* Wp = Wgt + (size_t)b * QQ * CC;
    const float* Cp = Ctx + (size_t)b * CC * DD;

    const int qr = tid >> 2;
    const int cg = tid & 3;
    const int cl = tid >> 4;
    const int dl = (tid & 15) * 2;

    ull acc[4] = {};

    {
        float4 w4 = *(const float4*)&Wp[qr * CC + cg * 4];
        Ws[0][cg*4+0][qr] = w4.x; Ws[0][cg*4+1][qr] = w4.y;
        Ws[0][cg*4+2][qr] = w4.z; Ws[0][cg*4+3][qr] = w4.w;
        float2 c2 = *(const float2*)&Cp[(size_t)cl * DD + d0 + dl];
        Cs[0][cl][dl] = c2.x; Cs[0][cl][dl+1] = c2.y;
    }
    __syncthreads();

    int buf = 0;
    for (int c0 = 16; c0 <= CC; c0 += 16) {
        float4 nw; float2 nc;
        const bool more = (c0 < CC);
        if (more) {
            nw = *(const float4*)&Wp[qr * CC + c0 + cg * 4];
            nc = *(const float2*)&Cp[(size_t)(c0 + cl) * DD + d0 + dl];
        }

        #pragma unroll
        for (int cc = 0; cc < 16; cc++) {
            float4 w4 = *(const float4*)&Ws[buf][cc][ty * 4];
            ull cv = *(const ull*)&Cs[buf][cc][tx * 2];
            fma2(acc[0], pack2(w4.x), cv);
            fma2(acc[1], pack2(w4.y), cv);
            fma2(acc[2], pack2(w4.z), cv);
            fma2(acc[3], pack2(w4.w), cv);
        }

        if (more) {
            const int nbuf = buf ^ 1;
            Ws[nbuf][cg*4+0][qr] = nw.x; Ws[nbuf][cg*4+1][qr] = nw.y;
            Ws[nbuf][cg*4+2][qr] = nw.z; Ws[nbuf][cg*4+3][qr] = nw.w;
            Cs[nbuf][cl][dl] = nc.x; Cs[nbuf][cl][dl+1] = nc.y;
        }
        __syncthreads();
        buf ^= 1;
    }

    #pragma unroll
    for (int i = 0; i < 4; i++) {
        float2 p = unpack2(acc[i]);
        const int q = ty * 4 + i;
        *(float2*)&out[(b * QQ + q) * DD + d0 + tx * 2] = p;
    }
}

// ---------------------------------------------------------------------------
extern "C" void kernel_launch(void* const* d_in, const int* in_sizes, int n_in,
                              void* d_out, int out_size)
{
    const float* query   = (const float*)d_in[0];
    const float* context = (const float*)d_in[1];
    const float* mask    = (const float*)d_in[2];
    const float* W_c     = (const float*)d_in[3];
    const float* b_c     = (const float*)d_in[4];
    const float* W_q     = (const float*)d_in[5];
    const float* W_o     = (const float*)d_in[6];
    const float* b_o     = (const float*)d_in[7];
    float* out = (float*)d_out;

    cudaFuncSetAttribute(tc_gemms, cudaFuncAttributeMaxDynamicSharedMemorySize,
                         TCG_SMEM);

    tc_gemms<<<144, 256, TCG_SMEM>>>(W_c, context, b_c, query, W_q);
    logits_softmax<<<128, 1024>>>(mask, W_o, b_o, out);
    out_gemm<<<128, 256>>>(context, out + WOFF, out);
}

// round 9
// speedup vs baseline: 2.4781x; 1.0934x over previous
#include <cuda_runtime.h>
#include <cuda_bf16.h>
#include <cstdint>

// Problem constants
#define BB 8
#define QQ 64
#define CC 512
#define DD 512
#define HH 256
#define EPSF 1e-5f
#define WOFF (BB * QQ * DD)

typedef unsigned long long ull;

__device__ float g_resq[BB * QQ * HH];        // [bq][h]
__device__ float g_rescT[BB * HH * CC];       // [b][h][c]

__device__ __forceinline__ float tanh_approx(float x) {
    float y;
    asm("tanh.approx.f32 %0, %1;" : "=f"(y) : "f"(x));
    return y;
}
__device__ __forceinline__ ull pack2(float x) {
    ull r; asm("mov.b64 %0, {%1, %1};" : "=l"(r) : "f"(x)); return r;
}
__device__ __forceinline__ void fma2(ull& d, ull a, ull b) {
    asm("fma.rn.f32x2 %0, %1, %2, %0;" : "+l"(d) : "l"(a), "l"(b));
}
__device__ __forceinline__ float2 unpack2(ull v) {
    float2 r; asm("mov.b64 {%0, %1}, %2;" : "=f"(r.x), "=f"(r.y) : "l"(v)); return r;
}
__device__ __forceinline__ uint32_t s2u(const void* p) {
    uint32_t a;
    asm("{ .reg .u64 t; cvta.to.shared.u64 t, %1; cvt.u32.u64 %0, t; }"
        : "=r"(a) : "l"(p));
    return a;
}
__device__ __forceinline__ void cp16(uint32_t s, const void* g) {
    asm volatile("cp.async.cg.shared.global [%0], [%1], 16;" :: "r"(s), "l"(g) : "memory");
}

#define MMA_TF32(c, a, b0, b1)                                            \
    asm volatile("mma.sync.aligned.m16n8k8.row.col.f32.tf32.tf32.f32 "    \
                 "{%0,%1,%2,%3}, {%4,%5,%6,%7}, {%8,%9}, {%0,%1,%2,%3};"  \
                 : "+f"((c)[0]), "+f"((c)[1]), "+f"((c)[2]), "+f"((c)[3]) \
                 : "r"((a)[0]), "r"((a)[1]), "r"((a)[2]), "r"((a)[3]),    \
                   "r"(b0), "r"(b1))

#define LDA 36                       // padded row (conflict-free frag LDS)
#define ATILE_U (128 * LDA)          // 4608 u32
#define BTILE_U (64 * LDA)           // 2304 u32
#define STAGE_U (ATILE_U + BTILE_U)  // 6912 u32
#define NSTAGE 3
#define TCG_SMEM (NSTAGE * STAGE_U * 4)   // 82944 B

// ---------------------------------------------------------------------------
// A: tf32 mma.sync GEMMs with cp.async 3-stage pipeline. 144 blocks x 256 thr.
//   blocks [0,128):  res_cT[b]: D[m=h(128)][n=c(64)] = Wc[h,:]·ctx[b][c,:]+bias
//   blocks [128,144): res_q:    D[m=bq(128)][n=h(64)] = q[bq,:]·Wq[h,:]
// fp32 copied raw into smem; tf32 MMA hardware-truncates mantissa.
// ---------------------------------------------------------------------------
__global__ __launch_bounds__(256, 1)
void tc_gemms(const float* __restrict__ Wc,
              const float* __restrict__ Ctx,
              const float* __restrict__ bc,
              const float* __restrict__ Qm,
              const float* __restrict__ Wq)
{
    extern __shared__ uint32_t smem[];   // [stage][ A 128x36 | B 64x36 ]
    const uint32_t smem_b = s2u(smem);

    const int tid  = threadIdx.x;
    const int wid  = tid >> 5;
    const int lane = tid & 31;
    const int g    = lane >> 2;
    const int tg   = lane & 3;

    const int mbase = (wid & 3) * 32;    // 4 warps over M
    const int nbase = (wid >> 2) * 32;   // 2 warps over N

    // Block role
    const float *Ap, *Bp;
    const float* biasp = nullptr;
    float* outp;
    int ldo;
    const int blk = blockIdx.x;
    if (blk < 128) {
        const int b  = blk >> 4;
        const int ht = (blk >> 3) & 1;
        const int ct = blk & 7;
        Ap    = Wc + (size_t)(ht * 128) * DD;
        Bp    = Ctx + (size_t)b * CC * DD + (size_t)(ct * 64) * DD;
        outp  = g_rescT + (size_t)b * HH * CC + (size_t)(ht * 128) * CC + ct * 64;
        ldo   = CC;
        biasp = bc + ht * 128;
    } else {
        const int blk2 = blk - 128;
        const int mt = blk2 >> 2;
        const int nt = blk2 & 3;
        Ap   = Qm + (size_t)(mt * 128) * DD;
        Bp   = Wq + (size_t)(nt * 64) * DD;
        outp = g_resq + (size_t)(mt * 128) * HH + nt * 64;
        ldo  = HH;
    }

    // staging coords: A 1024 float4 (4/thread), B 512 float4 (2/thread)
    int am[4], ak[4], bm[2], bk[2];
    #pragma unroll
    for (int i = 0; i < 4; i++) {
        const int f = tid + (i << 8);
        am[i] = f >> 3;
        ak[i] = (f & 7) << 2;
    }
    #pragma unroll
    for (int i = 0; i < 2; i++) {
        const int f = tid + (i << 8);
        bm[i] = f >> 3;
        bk[i] = (f & 7) << 2;
    }

    auto issue_stage = [&](int buf, int kt) {
        const uint32_t base = smem_b + buf * (STAGE_U * 4);
        #pragma unroll
        for (int i = 0; i < 4; i++)
            cp16(base + (am[i] * LDA + ak[i]) * 4,
                 Ap + (size_t)am[i] * DD + kt + ak[i]);
        #pragma unroll
        for (int i = 0; i < 2; i++)
            cp16(base + (ATILE_U + bm[i] * LDA + bk[i]) * 4,
                 Bp + (size_t)bm[i] * DD + kt + bk[i]);
        asm volatile("cp.async.commit_group;" ::: "memory");
    };

    float acc[2][4][4] = {};

    issue_stage(0, 0);
    issue_stage(1, 32);

    #pragma unroll 1
    for (int t = 0; t < 16; t++) {
        if (t < 14) {
            asm volatile("cp.async.wait_group 1;" ::: "memory");
        } else {
            asm volatile("cp.async.wait_group 0;" ::: "memory");
        }
        __syncthreads();

        if (t < 14) issue_stage((t + 2) % NSTAGE, (t + 2) * 32);

        const uint32_t* A_s = smem + (t % NSTAGE) * STAGE_U;
        const uint32_t* B_s = A_s + ATILE_U;
        #pragma unroll
        for (int ks = 0; ks < 4; ks++) {
            const int kc = ks * 8;
            uint32_t a[2][4];
            #pragma unroll
            for (int mt = 0; mt < 2; mt++) {
                const int rbase = (mbase + mt * 16 + g) * LDA + kc + tg;
                a[mt][0] = A_s[rbase];
                a[mt][1] = A_s[rbase + 8 * LDA];
                a[mt][2] = A_s[rbase + 4];
                a[mt][3] = A_s[rbase + 8 * LDA + 4];
            }
            #pragma unroll
            for (int nt = 0; nt < 4; nt++) {
                const int bbase = (nbase + nt * 8 + g) * LDA + kc + tg;
                const uint32_t b0 = B_s[bbase];
                const uint32_t b1 = B_s[bbase + 4];
                MMA_TF32(acc[0][nt], a[0], b0, b1);
                MMA_TF32(acc[1][nt], a[1], b0, b1);
            }
        }
    }

    // Epilogue
    #pragma unroll
    for (int mt = 0; mt < 2; mt++) {
        const int row0 = mbase + mt * 16 + g;
        const int row1 = row0 + 8;
        const float bi0 = biasp ? biasp[row0] : 0.f;
        const float bi1 = biasp ? biasp[row1] : 0.f;
        #pragma unroll
        for (int nt = 0; nt < 4; nt++) {
            const int col = nbase + nt * 8 + tg * 2;
            float2 o0; o0.x = acc[mt][nt][0] + bi0; o0.y = acc[mt][nt][1] + bi0;
            float2 o1; o1.x = acc[mt][nt][2] + bi1; o1.y = acc[mt][nt][3] + bi1;
            *(float2*)(outp + (size_t)row0 * ldo + col) = o0;
            *(float2*)(outp + (size_t)row1 * ldo + col) = o1;
        }
    }
}

// ---------------------------------------------------------------------------
// B: logits (tanh over H) + softmax; writes weights to out[WOFF..].
// 1024 threads, grid 128. h-range split across halves, combine in smem.
// ---------------------------------------------------------------------------
__global__ __launch_bounds__(1024)
void logits_softmax(const float* __restrict__ Maskp,
                    const float* __restrict__ Wo,
                    const float* __restrict__ bo_p,
                    float* __restrict__ out)
{
    const int blk  = blockIdx.x;       // 0..127
    const int b    = blk >> 4;
    const int q0   = (blk & 15) * 4;
    const int tid  = threadIdx.x;
    const int c    = tid & 511;
    const int half = tid >> 9;

    __shared__ float4 sh_rq[HH];
    __shared__ float  sh_wo[HH];
    __shared__ float4 sh_acc[CC];
    __shared__ float  sh_part[4][16];
    __shared__ float  sh_tot[4];

    if (tid < HH) {
        float4 r;
        r.x = g_resq[(b * QQ + q0 + 0) * HH + tid];
        r.y = g_resq[(b * QQ + q0 + 1) * HH + tid];
        r.z = g_resq[(b * QQ + q0 + 2) * HH + tid];
        r.w = g_resq[(b * QQ + q0 + 3) * HH + tid];
        sh_rq[tid] = r;
        sh_wo[tid] = Wo[tid];
    }
    __syncthreads();

    float a0 = 0.f, a1 = 0.f, a2 = 0.f, a3 = 0.f;
    {
        const int hbase = half << 7;
        const float* rc = g_rescT + (size_t)b * HH * CC + (size_t)hbase * CC + c;
        #pragma unroll 8
        for (int h = 0; h < 128; h++) {
            const float  a  = rc[(size_t)h * CC];
            const float4 rq = sh_rq[hbase + h];
            const float  w  = sh_wo[hbase + h];
            a0 += w * tanh_approx(a + rq.x);
            a1 += w * tanh_approx(a + rq.y);
            a2 += w * tanh_approx(a + rq.z);
            a3 += w * tanh_approx(a + rq.w);
        }
    }
    if (half == 0) {
        sh_acc[c] = make_float4(a0, a1, a2, a3);
    }
    __syncthreads();

    float e0, e1, e2, e3;
    if (half == 1) {
        const float4 p = sh_acc[c];
        const float bo = __ldg(bo_p);
        const float m  = Maskp[b * CC + c];
        e0 = m * __expf(a0 + p.x + bo);
        e1 = m * __expf(a1 + p.y + bo);
        e2 = m * __expf(a2 + p.z + bo);
        e3 = m * __expf(a3 + p.w + bo);

        float s0 = e0, s1 = e1, s2 = e2, s3 = e3;
        #pragma unroll
        for (int off = 16; off > 0; off >>= 1) {
            s0 += __shfl_xor_sync(0xffffffffu, s0, off);
            s1 += __shfl_xor_sync(0xffffffffu, s1, off);
            s2 += __shfl_xor_sync(0xffffffffu, s2, off);
            s3 += __shfl_xor_sync(0xffffffffu, s3, off);
        }
        const int lane = tid & 31, w2 = (tid >> 5) & 15;
        if (lane == 0) {
            sh_part[0][w2] = s0; sh_part[1][w2] = s1;
            sh_part[2][w2] = s2; sh_part[3][w2] = s3;
        }
    }
    __syncthreads();
    if (tid < 4) {
        float t = 0.f;
        #pragma unroll
        for (int i = 0; i < 16; i++) t += sh_part[tid][i];
        sh_tot[tid] = 1.f / (t + EPSF);
    }
    __syncthreads();

    if (half == 1) {
        out[WOFF + (b * QQ + q0 + 0) * CC + c] = e0 * sh_tot[0];
        out[WOFF + (b * QQ + q0 + 1) * CC + c] = e1 * sh_tot[1];
        out[WOFF + (b * QQ + q0 + 2) * CC + c] = e2 * sh_tot[2];
        out[WOFF + (b * QQ + q0 + 3) * CC + c] = e3 * sh_tot[3];
    }
}

// ---------------------------------------------------------------------------
// C: output[bq][d] = sum_c weights[bq][c] * ctx[b][c][d]
// Tiled GEMM: 64q x 32d per block, K=512, double-buffered, f32x2 FMA.
// ---------------------------------------------------------------------------
__global__ __launch_bounds__(256)
void out_gemm(const float* __restrict__ Ctx,
              const float* __restrict__ Wgt,
              float* __restrict__ out)
{
    const int blk = blockIdx.x;        // 0..127
    const int b   = blk >> 4;
    const int d0  = (blk & 15) * 32;
    const int tid = threadIdx.x;
    const int ty  = tid >> 4;
    const int tx  = tid & 15;

    __shared__ float Ws[2][16][68];
    __shared__ float Cs[2][16][34];

    const float* Wp = Wgt + (size_t)b * QQ * CC;
    const float* Cp = Ctx + (size_t)b * CC * DD;

    const int qr = tid >> 2;
    const int cg = tid & 3;
    const int cl = tid >> 4;
    const int dl = (tid & 15) * 2;

    ull acc[4] = {};

    {
        float4 w4 = *(const float4*)&Wp[qr * CC + cg * 4];
        Ws[0][cg*4+0][qr] = w4.x; Ws[0][cg*4+1][qr] = w4.y;
        Ws[0][cg*4+2][qr] = w4.z; Ws[0][cg*4+3][qr] = w4.w;
        float2 c2 = *(const float2*)&Cp[(size_t)cl * DD + d0 + dl];
        Cs[0][cl][dl] = c2.x; Cs[0][cl][dl+1] = c2.y;
    }
    __syncthreads();

    int buf = 0;
    for (int c0 = 16; c0 <= CC; c0 += 16) {
        float4 nw; float2 nc;
        const bool more = (c0 < CC);
        if (more) {
            nw = *(const float4*)&Wp[qr * CC + c0 + cg * 4];
            nc = *(const float2*)&Cp[(size_t)(c0 + cl) * DD + d0 + dl];
        }

        #pragma unroll
        for (int cc = 0; cc < 16; cc++) {
            float4 w4 = *(const float4*)&Ws[buf][cc][ty * 4];
            ull cv = *(const ull*)&Cs[buf][cc][tx * 2];
            fma2(acc[0], pack2(w4.x), cv);
            fma2(acc[1], pack2(w4.y), cv);
            fma2(acc[2], pack2(w4.z), cv);
            fma2(acc[3], pack2(w4.w), cv);
        }

        if (more) {
            const int nbuf = buf ^ 1;
            Ws[nbuf][cg*4+0][qr] = nw.x; Ws[nbuf][cg*4+1][qr] = nw.y;
            Ws[nbuf][cg*4+2][qr] = nw.z; Ws[nbuf][cg*4+3][qr] = nw.w;
            Cs[nbuf][cl][dl] = nc.x; Cs[nbuf][cl][dl+1] = nc.y;
        }
        __syncthreads();
        buf ^= 1;
    }

    #pragma unroll
    for (int i = 0; i < 4; i++) {
        float2 p = unpack2(acc[i]);
        const int q = ty * 4 + i;
        *(float2*)&out[(b * QQ + q) * DD + d0 + tx * 2] = p;
    }
}

// ---------------------------------------------------------------------------
extern "C" void kernel_launch(void* const* d_in, const int* in_sizes, int n_in,
                              void* d_out, int out_size)
{
    const float* query   = (const float*)d_in[0];
    const float* context = (const float*)d_in[1];
    const float* mask    = (const float*)d_in[2];
    const float* W_c     = (const float*)d_in[3];
    const float* b_c     = (const float*)d_in[4];
    const float* W_q     = (const float*)d_in[5];
    const float* W_o     = (const float*)d_in[6];
    const float* b_o     = (const float*)d_in[7];
    float* out = (float*)d_out;

    cudaFuncSetAttribute(tc_gemms, cudaFuncAttributeMaxDynamicSharedMemorySize,
                         TCG_SMEM);

    tc_gemms<<<144, 256, TCG_SMEM>>>(W_c, context, b_c, query, W_q);
    logits_softmax<<<128, 1024>>>(mask, W_o, b_o, out);
    out_gemm<<<128, 256>>>(context, out + WOFF, out);
}

// round 10
// speedup vs baseline: 2.4797x; 1.0006x over previous
#include <cuda_runtime.h>
#include <cuda_bf16.h>
#include <cstdint>

// Problem constants
#define BB 8
#define QQ 64
#define CC 512
#define DD 512
#define HH 256
#define EPSF 1e-5f
#define WOFF (BB * QQ * DD)

typedef unsigned long long ull;

__device__ float g_resq[BB * QQ * HH];        // [bq][h]
__device__ float g_rescT[BB * HH * CC];       // [b][h][c]

__device__ __forceinline__ float tanh_approx(float x) {
    float y;
    asm("tanh.approx.f32 %0, %1;" : "=f"(y) : "f"(x));
    return y;
}
__device__ __forceinline__ ull pack2(float x) {
    ull r; asm("mov.b64 %0, {%1, %1};" : "=l"(r) : "f"(x)); return r;
}
__device__ __forceinline__ void fma2(ull& d, ull a, ull b) {
    asm("fma.rn.f32x2 %0, %1, %2, %0;" : "+l"(d) : "l"(a), "l"(b));
}
__device__ __forceinline__ float2 unpack2(ull v) {
    float2 r; asm("mov.b64 {%0, %1}, %2;" : "=f"(r.x), "=f"(r.y) : "l"(v)); return r;
}
__device__ __forceinline__ uint32_t s2u(const void* p) {
    uint32_t a;
    asm("{ .reg .u64 t; cvta.to.shared.u64 t, %1; cvt.u32.u64 %0, t; }"
        : "=r"(a) : "l"(p));
    return a;
}
__device__ __forceinline__ void cp16(uint32_t s, const void* g) {
    asm volatile("cp.async.cg.shared.global [%0], [%1], 16;" :: "r"(s), "l"(g) : "memory");
}

#define MMA_TF32(c, a, b0, b1)                                            \
    asm volatile("mma.sync.aligned.m16n8k8.row.col.f32.tf32.tf32.f32 "    \
                 "{%0,%1,%2,%3}, {%4,%5,%6,%7}, {%8,%9}, {%0,%1,%2,%3};"  \
                 : "+f"((c)[0]), "+f"((c)[1]), "+f"((c)[2]), "+f"((c)[3]) \
                 : "r"((a)[0]), "r"((a)[1]), "r"((a)[2]), "r"((a)[3]),    \
                   "r"(b0), "r"(b1))

#define LDA 40                       // row pad: LDS.64 frag loads conflict-free
#define ATILE_U (128 * LDA)          // 5120 u32
#define BTILE_U (64 * LDA)           // 2560 u32
#define STAGE_U (ATILE_U + BTILE_U)  // 7680 u32
#define NSTAGE 3
#define TCG_SMEM (NSTAGE * STAGE_U * 4)   // 92160 B

// ---------------------------------------------------------------------------
// A: tf32 mma.sync GEMMs, cp.async 3-stage pipeline, 144 blocks x 256 thr.
// Fragment gather uses a k-slot permutation (sigma = [0,2,4,6,1,3,5,7], applied
// identically to A and B, leaving the dot product invariant) so each thread's
// two k-slots {tg, tg+4} live at adjacent smem positions {2tg, 2tg+1}:
// every fragment piece is ONE LDS.64 instead of two scalar LDS.
// ---------------------------------------------------------------------------
__global__ __launch_bounds__(256, 1)
void tc_gemms(const float* __restrict__ Wc,
              const float* __restrict__ Ctx,
              const float* __restrict__ bc,
              const float* __restrict__ Qm,
              const float* __restrict__ Wq)
{
    extern __shared__ uint32_t smem[];   // [stage][ A 128x40 | B 64x40 ]
    const uint32_t smem_b = s2u(smem);

    const int tid  = threadIdx.x;
    const int wid  = tid >> 5;
    const int lane = tid & 31;
    const int g    = lane >> 2;
    const int tg   = lane & 3;

    const int mbase = (wid & 3) * 32;    // 4 warps over M
    const int nbase = (wid >> 2) * 32;   // 2 warps over N

    // Block role
    const float *Ap, *Bp;
    const float* biasp = nullptr;
    float* outp;
    int ldo;
    const int blk = blockIdx.x;
    if (blk < 128) {
        const int b  = blk >> 4;
        const int ht = (blk >> 3) & 1;
        const int ct = blk & 7;
        Ap    = Wc + (size_t)(ht * 128) * DD;
        Bp    = Ctx + (size_t)b * CC * DD + (size_t)(ct * 64) * DD;
        outp  = g_rescT + (size_t)b * HH * CC + (size_t)(ht * 128) * CC + ct * 64;
        ldo   = CC;
        biasp = bc + ht * 128;
    } else {
        const int blk2 = blk - 128;
        const int mt = blk2 >> 2;
        const int nt = blk2 & 3;
        Ap   = Qm + (size_t)(mt * 128) * DD;
        Bp   = Wq + (size_t)(nt * 64) * DD;
        outp = g_resq + (size_t)(mt * 128) * HH + nt * 64;
        ldo  = HH;
    }

    // staging coords: A 1024 float4 (4/thread), B 512 float4 (2/thread)
    int am[4], ak[4], bm[2], bk[2];
    #pragma unroll
    for (int i = 0; i < 4; i++) {
        const int f = tid + (i << 8);
        am[i] = f >> 3;
        ak[i] = (f & 7) << 2;
    }
    #pragma unroll
    for (int i = 0; i < 2; i++) {
        const int f = tid + (i << 8);
        bm[i] = f >> 3;
        bk[i] = (f & 7) << 2;
    }

    auto issue_stage = [&](int buf, int kt) {
        const uint32_t base = smem_b + buf * (STAGE_U * 4);
        #pragma unroll
        for (int i = 0; i < 4; i++)
            cp16(base + (am[i] * LDA + ak[i]) * 4,
                 Ap + (size_t)am[i] * DD + kt + ak[i]);
        #pragma unroll
        for (int i = 0; i < 2; i++)
            cp16(base + (ATILE_U + bm[i] * LDA + bk[i]) * 4,
                 Bp + (size_t)bm[i] * DD + kt + bk[i]);
        asm volatile("cp.async.commit_group;" ::: "memory");
    };

    float acc[2][4][4] = {};

    issue_stage(0, 0);
    issue_stage(1, 32);

    const int foff = 2 * tg;   // position of this thread's k-slot pair in a group

    #pragma unroll 1
    for (int t = 0; t < 16; t++) {
        if (t < 14) {
            asm volatile("cp.async.wait_group 1;" ::: "memory");
        } else {
            asm volatile("cp.async.wait_group 0;" ::: "memory");
        }
        __syncthreads();

        if (t < 14) issue_stage((t + 2) % NSTAGE, (t + 2) * 32);

        const uint32_t* A_s = smem + (t % NSTAGE) * STAGE_U;
        const uint32_t* B_s = A_s + ATILE_U;
        #pragma unroll
        for (int ks = 0; ks < 4; ks++) {
            const int kc = ks * 8 + foff;
            uint32_t a[2][4];
            #pragma unroll
            for (int mt = 0; mt < 2; mt++) {
                const int rbase = (mbase + mt * 16 + g) * LDA + kc;
                const uint2 lo = *(const uint2*)&A_s[rbase];            // a0, a2
                const uint2 hi = *(const uint2*)&A_s[rbase + 8 * LDA];  // a1, a3
                a[mt][0] = lo.x; a[mt][2] = lo.y;
                a[mt][1] = hi.x; a[mt][3] = hi.y;
            }
            #pragma unroll
            for (int nt = 0; nt < 4; nt++) {
                const int bbase = (nbase + nt * 8 + g) * LDA + kc;
                const uint2 bv = *(const uint2*)&B_s[bbase];            // b0, b1
                MMA_TF32(acc[0][nt], a[0], bv.x, bv.y);
                MMA_TF32(acc[1][nt], a[1], bv.x, bv.y);
            }
        }
    }

    // Epilogue
    #pragma unroll
    for (int mt = 0; mt < 2; mt++) {
        const int row0 = mbase + mt * 16 + g;
        const int row1 = row0 + 8;
        const float bi0 = biasp ? biasp[row0] : 0.f;
        const float bi1 = biasp ? biasp[row1] : 0.f;
        #pragma unroll
        for (int nt = 0; nt < 4; nt++) {
            const int col = nbase + nt * 8 + tg * 2;
            float2 o0; o0.x = acc[mt][nt][0] + bi0; o0.y = acc[mt][nt][1] + bi0;
            float2 o1; o1.x = acc[mt][nt][2] + bi1; o1.y = acc[mt][nt][3] + bi1;
            *(float2*)(outp + (size_t)row0 * ldo + col) = o0;
            *(float2*)(outp + (size_t)row1 * ldo + col) = o1;
        }
    }
}

// ---------------------------------------------------------------------------
// B: logits (tanh over H) + softmax; writes weights to out[WOFF..].
// 1024 threads, grid 128. h-range split across halves, combine in smem.
// ---------------------------------------------------------------------------
__global__ __launch_bounds__(1024)
void logits_softmax(const float* __restrict__ Maskp,
                    const float* __restrict__ Wo,
                    const float* __restrict__ bo_p,
                    float* __restrict__ out)
{
    const int blk  = blockIdx.x;       // 0..127
    const int b    = blk >> 4;
    const int q0   = (blk & 15) * 4;
    const int tid  = threadIdx.x;
    const int c    = tid & 511;
    const int half = tid >> 9;

    __shared__ float4 sh_rq[HH];
    __shared__ float  sh_wo[HH];
    __shared__ float4 sh_acc[CC];
    __shared__ float  sh_part[4][16];
    __shared__ float  sh_tot[4];

    if (tid < HH) {
        float4 r;
        r.x = g_resq[(b * QQ + q0 + 0) * HH + tid];
        r.y = g_resq[(b * QQ + q0 + 1) * HH + tid];
        r.z = g_resq[(b * QQ + q0 + 2) * HH + tid];
        r.w = g_resq[(b * QQ + q0 + 3) * HH + tid];
        sh_rq[tid] = r;
        sh_wo[tid] = Wo[tid];
    }
    __syncthreads();

    float a0 = 0.f, a1 = 0.f, a2 = 0.f, a3 = 0.f;
    {
        const int hbase = half << 7;
        const float* rc = g_rescT + (size_t)b * HH * CC + (size_t)hbase * CC + c;
        #pragma unroll 8
        for (int h = 0; h < 128; h++) {
            const float  a  = rc[(size_t)h * CC];
            const float4 rq = sh_rq[hbase + h];
            const float  w  = sh_wo[hbase + h];
            a0 += w * tanh_approx(a + rq.x);
            a1 += w * tanh_approx(a + rq.y);
            a2 += w * tanh_approx(a + rq.z);
            a3 += w * tanh_approx(a + rq.w);
        }
    }
    if (half == 0) {
        sh_acc[c] = make_float4(a0, a1, a2, a3);
    }
    __syncthreads();

    float e0, e1, e2, e3;
    if (half == 1) {
        const float4 p = sh_acc[c];
        const float bo = __ldg(bo_p);
        const float m  = Maskp[b * CC + c];
        e0 = m * __expf(a0 + p.x + bo);
        e1 = m * __expf(a1 + p.y + bo);
        e2 = m * __expf(a2 + p.z + bo);
        e3 = m * __expf(a3 + p.w + bo);

        float s0 = e0, s1 = e1, s2 = e2, s3 = e3;
        #pragma unroll
        for (int off = 16; off > 0; off >>= 1) {
            s0 += __shfl_xor_sync(0xffffffffu, s0, off);
            s1 += __shfl_xor_sync(0xffffffffu, s1, off);
            s2 += __shfl_xor_sync(0xffffffffu, s2, off);
            s3 += __shfl_xor_sync(0xffffffffu, s3, off);
        }
        const int lane = tid & 31, w2 = (tid >> 5) & 15;
        if (lane == 0) {
            sh_part[0][w2] = s0; sh_part[1][w2] = s1;
            sh_part[2][w2] = s2; sh_part[3][w2] = s3;
        }
    }
    __syncthreads();
    if (tid < 4) {
        float t = 0.f;
        #pragma unroll
        for (int i = 0; i < 16; i++) t += sh_part[tid][i];
        sh_tot[tid] = 1.f / (t + EPSF);
    }
    __syncthreads();

    if (half == 1) {
        out[WOFF + (b * QQ + q0 + 0) * CC + c] = e0 * sh_tot[0];
        out[WOFF + (b * QQ + q0 + 1) * CC + c] = e1 * sh_tot[1];
        out[WOFF + (b * QQ + q0 + 2) * CC + c] = e2 * sh_tot[2];
        out[WOFF + (b * QQ + q0 + 3) * CC + c] = e3 * sh_tot[3];
    }
}

// ---------------------------------------------------------------------------
// C: output[bq][d] = sum_c weights[bq][c] * ctx[b][c][d]
// Tiled GEMM: 64q x 32d per block, K=512, double-buffered, f32x2 FMA.
// ---------------------------------------------------------------------------
__global__ __launch_bounds__(256)
void out_gemm(const float* __restrict__ Ctx,
              const float* __restrict__ Wgt,
              float* __restrict__ out)
{
    const int blk = blockIdx.x;        // 0..127
    const int b   = blk >> 4;
    const int d0  = (blk & 15) * 32;
    const int tid = threadIdx.x;
    const int ty  = tid >> 4;
    const int tx  = tid & 15;

    __shared__ float Ws[2][16][68];
    __shared__ float Cs[2][16][34];

    const float* Wp = Wgt + (size_t)b * QQ * CC;
    const float* Cp = Ctx + (size_t)b * CC * DD;

    const int qr = tid >> 2;
    const int cg = tid & 3;
    const int cl = tid >> 4;
    const int dl = (tid & 15) * 2;

    ull acc[4] = {};

    {
        float4 w4 = *(const float4*)&Wp[qr * CC + cg * 4];
        Ws[0][cg*4+0][qr] = w4.x; Ws[0][cg*4+1][qr] = w4.y;
        Ws[0][cg*4+2][qr] = w4.z; Ws[0][cg*4+3][qr] = w4.w;
        float2 c2 = *(const float2*)&Cp[(size_t)cl * DD + d0 + dl];
        Cs[0][cl][dl] = c2.x; Cs[0][cl][dl+1] = c2.y;
    }
    __syncthreads();

    int buf = 0;
    for (int c0 = 16; c0 <= CC; c0 += 16) {
        float4 nw; float2 nc;
        const bool more = (c0 < CC);
        if (more) {
            nw = *(const float4*)&Wp[qr * CC + c0 + cg * 4];
            nc = *(const float2*)&Cp[(size_t)(c0 + cl) * DD + d0 + dl];
        }

        #pragma unroll
        for (int cc = 0; cc < 16; cc++) {
            float4 w4 = *(const float4*)&Ws[buf][cc][ty * 4];
            ull cv = *(const ull*)&Cs[buf][cc][tx * 2];
            fma2(acc[0], pack2(w4.x), cv);
            fma2(acc[1], pack2(w4.y), cv);
            fma2(acc[2], pack2(w4.z), cv);
            fma2(acc[3], pack2(w4.w), cv);
        }

        if (more) {
            const int nbuf = buf ^ 1;
            Ws[nbuf][cg*4+0][qr] = nw.x; Ws[nbuf][cg*4+1][qr] = nw.y;
            Ws[nbuf][cg*4+2][qr] = nw.z; Ws[nbuf][cg*4+3][qr] = nw.w;
            Cs[nbuf][cl][dl] = nc.x; Cs[nbuf][cl][dl+1] = nc.y;
        }
        __syncthreads();
        buf ^= 1;
    }

    #pragma unroll
    for (int i = 0; i < 4; i++) {
        float2 p = unpack2(acc[i]);
        const int q = ty * 4 + i;
        *(float2*)&out[(b * QQ + q) * DD + d0 + tx * 2] = p;
    }
}

// ---------------------------------------------------------------------------
extern "C" void kernel_launch(void* const* d_in, const int* in_sizes, int n_in,
                              void* d_out, int out_size)
{
    const float* query   = (const float*)d_in[0];
    const float* context = (const float*)d_in[1];
    const float* mask    = (const float*)d_in[2];
    const float* W_c     = (const float*)d_in[3];
    const float* b_c     = (const float*)d_in[4];
    const float* W_q     = (const float*)d_in[5];
    const float* W_o     = (const float*)d_in[6];
    const float* b_o     = (const float*)d_in[7];
    float* out = (float*)d_out;

    cudaFuncSetAttribute(tc_gemms, cudaFuncAttributeMaxDynamicSharedMemorySize,
                         TCG_SMEM);

    tc_gemms<<<144, 256, TCG_SMEM>>>(W_c, context, b_c, query, W_q);
    logits_softmax<<<128, 1024>>>(mask, W_o, b_o, out);
    out_gemm<<<128, 256>>>(context, out + WOFF, out);
}